// round 2
// baseline (speedup 1.0000x reference)
#include <cuda_runtime.h>
#include <math.h>

#define BATCH 2
#define SEQ   2048
#define HID   2048
#define NH    16
#define DNOPE 128
#define DROPE 64
#define DV    128
#define DQK   192
#define LORA  512
#define ROWS  (BATCH*SEQ)   // 4096

// ---------------- scratch (static device memory; no allocations) ----------------
__device__ float g_qtmp[(size_t)ROWS*1536];
__device__ float g_qbig[(size_t)ROWS*3072];
__device__ float g_c   [(size_t)ROWS*576];
__device__ float g_kv  [(size_t)ROWS*4096];
__device__ float g_Q   [(size_t)BATCH*NH*SEQ*DQK];
__device__ float g_Km  [(size_t)BATCH*NH*SEQ*DQK];
__device__ float g_Vm  [(size_t)BATCH*NH*SEQ*DV];
__device__ float g_ctx [(size_t)ROWS*NH*DV];
__device__ float g_attn_fb[(size_t)BATCH*NH*SEQ*SEQ];  // fallback if attn not in d_out

// ---------------- block reductions ----------------
__device__ __forceinline__ float blockReduceSum(float v) {
    __shared__ float sh[32];
    int lane = threadIdx.x & 31, w = threadIdx.x >> 5;
    #pragma unroll
    for (int o = 16; o > 0; o >>= 1) v += __shfl_xor_sync(0xffffffffu, v, o);
    __syncthreads();
    if (lane == 0) sh[w] = v;
    __syncthreads();
    int nw = (blockDim.x + 31) >> 5;
    float r = (threadIdx.x < nw) ? sh[threadIdx.x] : 0.0f;
    if (w == 0) {
        #pragma unroll
        for (int o = 16; o > 0; o >>= 1) r += __shfl_xor_sync(0xffffffffu, r, o);
        if (lane == 0) sh[0] = r;
    }
    __syncthreads();
    return sh[0];
}

__device__ __forceinline__ float blockReduceMax(float v) {
    __shared__ float sh[32];
    int lane = threadIdx.x & 31, w = threadIdx.x >> 5;
    #pragma unroll
    for (int o = 16; o > 0; o >>= 1) v = fmaxf(v, __shfl_xor_sync(0xffffffffu, v, o));
    __syncthreads();
    if (lane == 0) sh[w] = v;
    __syncthreads();
    int nw = (blockDim.x + 31) >> 5;
    float r = (threadIdx.x < nw) ? sh[threadIdx.x] : -INFINITY;
    if (w == 0) {
        #pragma unroll
        for (int o = 16; o > 0; o >>= 1) r = fmaxf(r, __shfl_xor_sync(0xffffffffu, r, o));
        if (lane == 0) sh[0] = r;
    }
    __syncthreads();
    return sh[0];
}

// ---------------- generic NT GEMM: C[m,n] = alpha * sum_k A[m,k]*B[n,k] ----------------
// 128x128 tile, BK=8, 256 threads, 8x8 microtile. Requires M%128==0, K%8==0.
// N guarded. Batched via z: base += (z/zdiv)*s1 + (z%zdiv)*s2 for each of A,B,C.
// causal==1: skip tiles with n0 > m0 entirely (fully masked; softmax zero-fills).
__global__ __launch_bounds__(256, 2) void gemm_nt(
    const float* __restrict__ A, const float* __restrict__ B, float* __restrict__ C,
    int M, int N, int K, int lda, int ldb, int ldc,
    int zdiv, long long sA1, long long sA2,
    long long sB1, long long sB2, long long sC1, long long sC2,
    float alpha, int causal)
{
    int z  = blockIdx.z;
    int m0 = blockIdx.y * 128;
    int n0 = blockIdx.x * 128;
    if (causal && n0 > m0) return;

    const float* Ab = A + (long long)(z / zdiv) * sA1 + (long long)(z % zdiv) * sA2;
    const float* Bb = B + (long long)(z / zdiv) * sB1 + (long long)(z % zdiv) * sB2;
    float*       Cb = C + (long long)(z / zdiv) * sC1 + (long long)(z % zdiv) * sC2;

    __shared__ float As[8][128];
    __shared__ float Bs[8][128];

    int t  = threadIdx.x;
    int tx = t & 15, ty = t >> 4;
    int lrow = t >> 1, lc4 = (t & 1) * 4;

    float acc[8][8];
    #pragma unroll
    for (int i = 0; i < 8; i++)
        #pragma unroll
        for (int j = 0; j < 8; j++) acc[i][j] = 0.0f;

    const float* aptr = Ab + (long long)(m0 + lrow) * lda + lc4;
    bool bvalid = (n0 + lrow) < N;
    const float* bptr = Bb + (long long)(n0 + lrow) * ldb + lc4;

    for (int k0 = 0; k0 < K; k0 += 8) {
        float4 av = *(const float4*)(aptr + k0);
        float4 bv = bvalid ? *(const float4*)(bptr + k0) : make_float4(0.f, 0.f, 0.f, 0.f);
        As[lc4 + 0][lrow] = av.x; As[lc4 + 1][lrow] = av.y;
        As[lc4 + 2][lrow] = av.z; As[lc4 + 3][lrow] = av.w;
        Bs[lc4 + 0][lrow] = bv.x; Bs[lc4 + 1][lrow] = bv.y;
        Bs[lc4 + 2][lrow] = bv.z; Bs[lc4 + 3][lrow] = bv.w;
        __syncthreads();
        #pragma unroll
        for (int kk = 0; kk < 8; kk++) {
            float a[8], b[8];
            #pragma unroll
            for (int i = 0; i < 8; i++) a[i] = As[kk][ty * 8 + i];
            #pragma unroll
            for (int j = 0; j < 8; j++) b[j] = Bs[kk][tx * 8 + j];
            #pragma unroll
            for (int i = 0; i < 8; i++)
                #pragma unroll
                for (int j = 0; j < 8; j++) acc[i][j] += a[i] * b[j];
        }
        __syncthreads();
    }

    #pragma unroll
    for (int i = 0; i < 8; i++) {
        long long roff = (long long)(m0 + ty * 8 + i) * ldc;
        #pragma unroll
        for (int j4 = 0; j4 < 8; j4 += 4) {
            int col = n0 + tx * 8 + j4;
            if (col + 3 < N) {
                float4 st = make_float4(acc[i][j4] * alpha, acc[i][j4 + 1] * alpha,
                                        acc[i][j4 + 2] * alpha, acc[i][j4 + 3] * alpha);
                *(float4*)(Cb + roff + col) = st;
            } else {
                #pragma unroll
                for (int j = 0; j < 4; j++)
                    if (col + j < N) Cb[roff + col + j] = acc[i][j4 + j] * alpha;
            }
        }
    }
}

// ---------------- NN GEMM with N==128: C[m,n] = sum_k A[m,k]*B[k,n] ----------------
// causal==1: k loop truncated at m0+128 (attn beyond is zero anyway).
__global__ __launch_bounds__(256, 2) void gemm_nn128(
    const float* __restrict__ A, const float* __restrict__ B, float* __restrict__ C,
    int M, int K, int lda, int ldb, int ldc,
    int zdiv, long long sA1, long long sA2,
    long long sB1, long long sB2, long long sC1, long long sC2,
    int causal)
{
    int z  = blockIdx.z;
    int m0 = blockIdx.y * 128;

    const float* Ab = A + (long long)(z / zdiv) * sA1 + (long long)(z % zdiv) * sA2;
    const float* Bb = B + (long long)(z / zdiv) * sB1 + (long long)(z % zdiv) * sB2;
    float*       Cb = C + (long long)(z / zdiv) * sC1 + (long long)(z % zdiv) * sC2;

    __shared__ float As[8][128];
    __shared__ float Bs[8][128];

    int t  = threadIdx.x;
    int tx = t & 15, ty = t >> 4;
    int arow = t >> 1, ac4 = (t & 1) * 4;
    int brow = t >> 5, bc4 = (t & 31) * 4;

    float acc[8][8];
    #pragma unroll
    for (int i = 0; i < 8; i++)
        #pragma unroll
        for (int j = 0; j < 8; j++) acc[i][j] = 0.0f;

    int kEnd = K;
    if (causal) { int ke = m0 + 128; kEnd = (ke < K) ? ke : K; }

    for (int k0 = 0; k0 < kEnd; k0 += 8) {
        float4 av = *(const float4*)(Ab + (long long)(m0 + arow) * lda + k0 + ac4);
        float4 bv = *(const float4*)(Bb + (long long)(k0 + brow) * ldb + bc4);
        As[ac4 + 0][arow] = av.x; As[ac4 + 1][arow] = av.y;
        As[ac4 + 2][arow] = av.z; As[ac4 + 3][arow] = av.w;
        *(float4*)&Bs[brow][bc4] = bv;
        __syncthreads();
        #pragma unroll
        for (int kk = 0; kk < 8; kk++) {
            float a[8], b[8];
            #pragma unroll
            for (int i = 0; i < 8; i++) a[i] = As[kk][ty * 8 + i];
            #pragma unroll
            for (int j = 0; j < 8; j++) b[j] = Bs[kk][tx * 8 + j];
            #pragma unroll
            for (int i = 0; i < 8; i++)
                #pragma unroll
                for (int j = 0; j < 8; j++) acc[i][j] += a[i] * b[j];
        }
        __syncthreads();
    }

    #pragma unroll
    for (int i = 0; i < 8; i++) {
        long long roff = (long long)(m0 + ty * 8 + i) * ldc;
        #pragma unroll
        for (int j4 = 0; j4 < 8; j4 += 4) {
            int col = tx * 8 + j4;
            float4 st = make_float4(acc[i][j4], acc[i][j4 + 1], acc[i][j4 + 2], acc[i][j4 + 3]);
            *(float4*)(Cb + roff + col) = st;
        }
    }
}

// ---------------- RMSNorm (in place, block per row) ----------------
__global__ __launch_bounds__(256) void rmsnorm_kernel(
    float* __restrict__ x, const float* __restrict__ w, int W, int stride)
{
    float* row = x + (long long)blockIdx.x * stride;
    float ss = 0.0f;
    for (int i = threadIdx.x; i < W; i += blockDim.x) { float v = row[i]; ss += v * v; }
    ss = blockReduceSum(ss);
    float sc = rsqrtf(ss / (float)W + 1e-6f);
    for (int i = threadIdx.x; i < W; i += blockDim.x) row[i] = row[i] * sc * w[i];
}

// ---------------- RoPE + pack Q/K/V into contiguous per-(b,h) layouts ----------------
__global__ __launch_bounds__(256) void rope_pack(
    const float* __restrict__ q,   // [ROWS, 3072] = [b,s,h,192]
    const float* __restrict__ c,   // [ROWS, 576]  (cols 512..575 = k_rope)
    const float* __restrict__ kv,  // [ROWS, 4096] = [b,s,h,256]
    float* __restrict__ Qo,        // [B,NH,S,192]
    float* __restrict__ Ko,        // [B,NH,S,192]
    float* __restrict__ Vo)        // [B,NH,S,128]
{
    int row = blockIdx.x;         // b*SEQ + s
    int b = row / SEQ, s = row % SEQ;
    int t = threadIdx.x;

    __shared__ float cs[32], sn[32], kr[64];
    if (t < 32) {
        float f = exp10f(-(float)t / 8.0f);      // 10000^(-t/32) = 10^(-t/8)
        float ang = (float)s * f;
        sincosf(ang, &sn[t], &cs[t]);
    }
    __syncthreads();
    if (t < 64) {
        const float* kx = c + (long long)row * 576 + 512;
        int j = t;
        float v;
        if (j < 32) v = kx[2 * j] * cs[j] - kx[2 * j + 1] * sn[j];
        else { int i = j - 32; v = kx[2 * i + 1] * cs[i] + kx[2 * i] * sn[i]; }
        kr[j] = v;
    }
    __syncthreads();

    const float* qrow = q + (long long)row * 3072;
    for (int idx = t; idx < NH * DQK; idx += 256) {
        int h = idx / DQK, d = idx % DQK;
        float v;
        if (d < DNOPE) v = qrow[h * DQK + d];
        else {
            int j = d - DNOPE;
            const float* qx = qrow + h * DQK + DNOPE;
            if (j < 32) v = qx[2 * j] * cs[j] - qx[2 * j + 1] * sn[j];
            else { int i = j - 32; v = qx[2 * i + 1] * cs[i] + qx[2 * i] * sn[i]; }
        }
        Qo[((long long)(b * NH + h) * SEQ + s) * DQK + d] = v;
    }

    const float* kvrow = kv + (long long)row * 4096;
    for (int idx = t; idx < NH * DQK; idx += 256) {
        int h = idx / DQK, d = idx % DQK;
        float v = (d < DNOPE) ? kvrow[h * 256 + d] : kr[d - DNOPE];
        Ko[((long long)(b * NH + h) * SEQ + s) * DQK + d] = v;
    }
    for (int idx = t; idx < NH * DV; idx += 256) {
        int h = idx / DV, d = idx % DV;
        Vo[((long long)(b * NH + h) * SEQ + s) * DV + d] = kvrow[h * 256 + DNOPE + d];
    }
}

// ---------------- causal softmax, in place, register-resident row ----------------
__global__ __launch_bounds__(128) void softmax_causal(float* __restrict__ attn)
{
    long long r = blockIdx.x;     // (b*NH+h)*SEQ + q
    int q = (int)(r % SEQ);
    float* row = attn + r * SEQ;
    int t = threadIdx.x;
    int len = q + 1;

    float vals[16];
    float mx = -INFINITY;
    #pragma unroll
    for (int it = 0; it < 16; it++) {
        int i = t + it * 128;
        float v = (i < len) ? row[i] : -INFINITY;
        vals[it] = v;
        mx = fmaxf(mx, v);
    }
    mx = blockReduceMax(mx);

    float sum = 0.0f;
    #pragma unroll
    for (int it = 0; it < 16; it++) {
        int i = t + it * 128;
        float e = (i < len) ? __expf(vals[it] - mx) : 0.0f;
        vals[it] = e;
        sum += e;
    }
    sum = blockReduceSum(sum);
    float inv = 1.0f / sum;

    #pragma unroll
    for (int it = 0; it < 16; it++) {
        int i = t + it * 128;
        row[i] = (i < len) ? vals[it] * inv : 0.0f;   // zero-fill masked tail
    }
}

// ---------------- host launch ----------------
extern "C" void kernel_launch(void* const* d_in, const int* in_sizes, int n_in,
                              void* d_out, int out_size) {
    const float* hidden    = (const float*)d_in[0];
    // d_in[1] = position_ids (== arange(S), recomputed on device)
    // d_in[2] = attention_mask (== causal tril, structural)
    const float* w_q_down  = (const float*)d_in[3];
    const float* q_norm_w  = (const float*)d_in[4];
    const float* w_q_up    = (const float*)d_in[5];
    const float* w_kv_down = (const float*)d_in[6];
    const float* kv_norm_w = (const float*)d_in[7];
    const float* w_kv_up   = (const float*)d_in[8];
    const float* w_out     = (const float*)d_in[9];
    float* outp = (float*)d_out;

    void* p;
    float *qtmp, *qbig, *c, *kv, *Q, *Kk, *V, *ctx, *attn_fb;
    cudaGetSymbolAddress(&p, g_qtmp);   qtmp    = (float*)p;
    cudaGetSymbolAddress(&p, g_qbig);   qbig    = (float*)p;
    cudaGetSymbolAddress(&p, g_c);      c       = (float*)p;
    cudaGetSymbolAddress(&p, g_kv);     kv      = (float*)p;
    cudaGetSymbolAddress(&p, g_Q);      Q       = (float*)p;
    cudaGetSymbolAddress(&p, g_Km);     Kk      = (float*)p;
    cudaGetSymbolAddress(&p, g_Vm);     V       = (float*)p;
    cudaGetSymbolAddress(&p, g_ctx);    ctx     = (float*)p;
    cudaGetSymbolAddress(&p, g_attn_fb); attn_fb = (float*)p;

    const long long OUT_ELEMS  = (long long)ROWS * HID;             // 8,388,608
    const long long ATTN_ELEMS = (long long)BATCH * NH * SEQ * SEQ; // 134,217,728
    float* attn = ((long long)out_size >= OUT_ELEMS + ATTN_ELEMS) ? (outp + OUT_ELEMS)
                                                                  : attn_fb;

    dim3 thr(256);

    // q = hidden @ w_q_down^T   [4096,1536]
    gemm_nt<<<dim3(1536 / 128, ROWS / 128, 1), thr>>>(
        hidden, w_q_down, qtmp, ROWS, 1536, HID, HID, HID, 1536,
        1, 0, 0, 0, 0, 0, 0, 1.0f, 0);
    rmsnorm_kernel<<<ROWS, 256>>>(qtmp, q_norm_w, 1536, 1536);

    // q = qn @ w_q_up^T   [4096,3072]
    gemm_nt<<<dim3(3072 / 128, ROWS / 128, 1), thr>>>(
        qtmp, w_q_up, qbig, ROWS, 3072, 1536, 1536, 1536, 3072,
        1, 0, 0, 0, 0, 0, 0, 1.0f, 0);

    // c = hidden @ w_kv_down^T   [4096,576]
    gemm_nt<<<dim3((576 + 127) / 128, ROWS / 128, 1), thr>>>(
        hidden, w_kv_down, c, ROWS, 576, HID, HID, HID, 576,
        1, 0, 0, 0, 0, 0, 0, 1.0f, 0);
    rmsnorm_kernel<<<ROWS, 256>>>(c, kv_norm_w, 512, 576);

    // kv = ckv_n @ w_kv_up^T   [4096,4096]
    gemm_nt<<<dim3(4096 / 128, ROWS / 128, 1), thr>>>(
        c, w_kv_up, kv, ROWS, 4096, 512, 576, 512, 4096,
        1, 0, 0, 0, 0, 0, 0, 1.0f, 0);

    // RoPE + pack
    rope_pack<<<ROWS, 256>>>(qbig, c, kv, Q, Kk, V);

    // scores = Q K^T / sqrt(192), causal-skipped, batched over 32 (b,h)
    float alpha = 1.0f / sqrtf((float)DQK);
    gemm_nt<<<dim3(SEQ / 128, SEQ / 128, BATCH * NH), thr>>>(
        Q, Kk, attn, SEQ, SEQ, DQK, DQK, DQK, SEQ,
        1, (long long)SEQ * DQK, 0,
        (long long)SEQ * DQK, 0,
        (long long)SEQ * SEQ, 0,
        alpha, 1);

    // softmax (also zero-fills masked region of attn output)
    softmax_causal<<<BATCH * NH * SEQ, 128>>>(attn);

    // ctx = attn @ V, causal k-truncated; written directly as [B,S,H*V]
    gemm_nn128<<<dim3(1, SEQ / 128, BATCH * NH), thr>>>(
        attn, V, ctx, SEQ, SEQ, SEQ, DV, NH * DV,
        NH,
        (long long)NH * SEQ * SEQ, (long long)SEQ * SEQ,
        (long long)NH * SEQ * DV,  (long long)SEQ * DV,
        (long long)SEQ * NH * DV,  (long long)DV,
        1);

    // out = ctx @ w_out^T   [4096,2048]
    gemm_nt<<<dim3(HID / 128, ROWS / 128, 1), thr>>>(
        ctx, w_out, outp, ROWS, HID, NH * DV, NH * DV, NH * DV, HID,
        1, 0, 0, 0, 0, 0, 0, 1.0f, 0);
}

// round 4
// speedup vs baseline: 2.8721x; 2.8721x over previous
#include <cuda_runtime.h>
#include <math.h>
#include <stdint.h>

#define BATCH 2
#define SEQ   2048
#define HID   2048
#define NH    16
#define DNOPE 128
#define DROPE 64
#define DV    128
#define DQK   192
#define LORA  512
#define ROWS  (BATCH*SEQ)   // 4096

// ---------------- scratch (static device memory; no allocations) ----------------
__device__ float g_qtmp[(size_t)ROWS*1536];
__device__ float g_qbig[(size_t)ROWS*3072];
__device__ float g_c   [(size_t)ROWS*576];
__device__ float g_kv  [(size_t)ROWS*4096];
__device__ float g_Q   [(size_t)BATCH*NH*SEQ*DQK];
__device__ float g_Km  [(size_t)BATCH*NH*SEQ*DQK];
__device__ float g_Vt  [(size_t)BATCH*NH*DV*SEQ];     // V transposed per (b,h): [DV][SEQ]
__device__ float g_ctx [(size_t)ROWS*NH*DV];
__device__ float g_attn_fb[(size_t)BATCH*NH*SEQ*SEQ];

__device__ __forceinline__ uint32_t f2tf(float x) {
    uint32_t r; asm("cvt.rna.tf32.f32 %0, %1;" : "=r"(r) : "f"(x)); return r;
}

#define MMA_TF32(ac, ar, br)                                                      \
    asm volatile("mma.sync.aligned.m16n8k8.row.col.f32.tf32.tf32.f32 "            \
                 "{%0,%1,%2,%3}, {%4,%5,%6,%7}, {%8,%9}, {%0,%1,%2,%3};"          \
                 : "+f"((ac)[0]), "+f"((ac)[1]), "+f"((ac)[2]), "+f"((ac)[3])     \
                 : "r"((ar)[0]), "r"((ar)[1]), "r"((ar)[2]), "r"((ar)[3]),        \
                   "r"((br)[0]), "r"((br)[1]))

// ---------------- tf32 mma.sync NT GEMM ----------------
// C[m,n] = alpha * sum_k A[m,k] * B[n,k]
// CTA 128x128, BK=32, 8 warps (warp tile 64x32 = 4x4 of m16n8k8).
// SMEM: [row][32] tf32, k-index XOR-swizzled by (row&7)*4 -> conflict-free
// STS.128 staging AND LDS.32 fragment loads.
// mode: 0 dense, 1 causal tile-skip, 2 causal K-truncation.
#define GSMEM_WORDS (2 * 8192)          // 2 buffers x (A 4096 + B 4096 words)
#define GSMEM_BYTES (GSMEM_WORDS * 4)   // 64 KB

__global__ __launch_bounds__(256, 1) void gemm_tc(
    const float* __restrict__ A, const float* __restrict__ B, float* __restrict__ C,
    int M, int N, int K, int lda, int ldb, int ldc,
    int zdiv, long long sA1, long long sA2,
    long long sB1, long long sB2, long long sC1, long long sC2,
    float alpha, int mode)
{
    int z  = blockIdx.z;
    int m0 = blockIdx.y * 128;
    int n0 = blockIdx.x * 128;
    if (mode == 1 && n0 > m0) return;

    const float* Ab = A + (long long)(z / zdiv) * sA1 + (long long)(z % zdiv) * sA2;
    const float* Bb = B + (long long)(z / zdiv) * sB1 + (long long)(z % zdiv) * sB2;
    float*       Cb = C + (long long)(z / zdiv) * sC1 + (long long)(z % zdiv) * sC2;

    extern __shared__ uint32_t sm[];

    int t    = threadIdx.x;
    int lane = t & 31;
    int wid  = t >> 5;
    int g    = lane >> 2;       // groupID 0..7
    int t4   = lane & 3;        // threadID_in_group 0..3
    int wm   = wid >> 2;        // 0..1  -> M offset wm*64
    int wn   = wid & 3;         // 0..3  -> N offset wn*32

    int kEnd = K;
    if (mode == 2) { int ke = m0 + 128; kEnd = (ke < K) ? ke : K; }
    int nk = kEnd >> 5;         // BK = 32

    float acc[4][4][4];
    #pragma unroll
    for (int mi = 0; mi < 4; mi++)
        #pragma unroll
        for (int ni = 0; ni < 4; ni++)
            #pragma unroll
            for (int r = 0; r < 4; r++) acc[mi][ni][r] = 0.0f;

    // staging mapping: f = i*256+t ; row = f>>3 (0..127), kc = f&7 (float4 col)
    int srow = t >> 3;          // base row for i-loop (row = srow + i*32)
    int skc  = t & 7;

    float4 ra[4], rb[4];

    // ---- load chunk into regs
    auto ldg_chunk = [&](int k0) {
        #pragma unroll
        for (int i = 0; i < 4; i++) {
            int row = srow + i * 32;
            ra[i] = *(const float4*)(Ab + (size_t)(m0 + row) * lda + k0 + skc * 4);
            if (n0 + row < N)
                rb[i] = *(const float4*)(Bb + (size_t)(n0 + row) * ldb + k0 + skc * 4);
            else
                rb[i] = make_float4(0.f, 0.f, 0.f, 0.f);
        }
    };
    // ---- convert + store regs into buffer b
    auto sts_chunk = [&](int b) {
        uint32_t* A_ = sm + b * 8192;
        uint32_t* B_ = A_ + 4096;
        #pragma unroll
        for (int i = 0; i < 4; i++) {
            int row = srow + i * 32;
            int w   = row * 32 + ((skc * 4) ^ ((row & 7) * 4));
            *(uint4*)(A_ + w) = make_uint4(f2tf(ra[i].x), f2tf(ra[i].y), f2tf(ra[i].z), f2tf(ra[i].w));
            *(uint4*)(B_ + w) = make_uint4(f2tf(rb[i].x), f2tf(rb[i].y), f2tf(rb[i].z), f2tf(rb[i].w));
        }
    };
    // ---- mma over buffer b
    auto mma_chunk = [&](int b) {
        const uint32_t* A_ = sm + b * 8192;
        const uint32_t* B_ = A_ + 4096;
        int xg = g * 4;
        #pragma unroll
        for (int ks = 0; ks < 4; ks++) {
            int kb = ks * 8;
            int x0 = (kb + t4)     ^ xg;
            int x1 = (kb + t4 + 4) ^ xg;
            uint32_t af[4][4], bfr[4][2];
            #pragma unroll
            for (int mi = 0; mi < 4; mi++) {
                int r0 = wm * 64 + mi * 16 + g;
                af[mi][0] = A_[r0 * 32 + x0];
                af[mi][1] = A_[(r0 + 8) * 32 + x0];
                af[mi][2] = A_[r0 * 32 + x1];
                af[mi][3] = A_[(r0 + 8) * 32 + x1];
            }
            #pragma unroll
            for (int ni = 0; ni < 4; ni++) {
                int c0 = wn * 32 + ni * 8 + g;
                bfr[ni][0] = B_[c0 * 32 + x0];
                bfr[ni][1] = B_[c0 * 32 + x1];
            }
            #pragma unroll
            for (int mi = 0; mi < 4; mi++)
                #pragma unroll
                for (int ni = 0; ni < 4; ni++)
                    MMA_TF32(acc[mi][ni], af[mi], bfr[ni]);
        }
    };

    // prologue
    ldg_chunk(0);
    sts_chunk(0);
    __syncthreads();

    for (int kt = 0; kt < nk; kt++) {
        int b = kt & 1;
        if (kt + 1 < nk) ldg_chunk((kt + 1) << 5);
        mma_chunk(b);
        if (kt + 1 < nk) sts_chunk(b ^ 1);
        __syncthreads();
    }

    // epilogue
    #pragma unroll
    for (int mi = 0; mi < 4; mi++) {
        int row = m0 + wm * 64 + mi * 16 + g;
        #pragma unroll
        for (int ni = 0; ni < 4; ni++) {
            int col = n0 + wn * 32 + ni * 8 + 2 * t4;
            if (col < N) {
                float2 v0 = make_float2(alpha * acc[mi][ni][0], alpha * acc[mi][ni][1]);
                float2 v1 = make_float2(alpha * acc[mi][ni][2], alpha * acc[mi][ni][3]);
                *(float2*)(Cb + (size_t)row * ldc + col)       = v0;
                *(float2*)(Cb + (size_t)(row + 8) * ldc + col) = v1;
            }
        }
    }
}

// ---------------- block reductions ----------------
__device__ __forceinline__ float blockReduceSum(float v) {
    __shared__ float sh[32];
    int lane = threadIdx.x & 31, w = threadIdx.x >> 5;
    #pragma unroll
    for (int o = 16; o > 0; o >>= 1) v += __shfl_xor_sync(0xffffffffu, v, o);
    __syncthreads();
    if (lane == 0) sh[w] = v;
    __syncthreads();
    int nw = (blockDim.x + 31) >> 5;
    float r = (threadIdx.x < nw) ? sh[threadIdx.x] : 0.0f;
    if (w == 0) {
        #pragma unroll
        for (int o = 16; o > 0; o >>= 1) r += __shfl_xor_sync(0xffffffffu, r, o);
        if (lane == 0) sh[0] = r;
    }
    __syncthreads();
    return sh[0];
}
__device__ __forceinline__ float blockReduceMax(float v) {
    __shared__ float sh[32];
    int lane = threadIdx.x & 31, w = threadIdx.x >> 5;
    #pragma unroll
    for (int o = 16; o > 0; o >>= 1) v = fmaxf(v, __shfl_xor_sync(0xffffffffu, v, o));
    __syncthreads();
    if (lane == 0) sh[w] = v;
    __syncthreads();
    int nw = (blockDim.x + 31) >> 5;
    float r = (threadIdx.x < nw) ? sh[threadIdx.x] : -INFINITY;
    if (w == 0) {
        #pragma unroll
        for (int o = 16; o > 0; o >>= 1) r = fmaxf(r, __shfl_xor_sync(0xffffffffu, r, o));
        if (lane == 0) sh[0] = r;
    }
    __syncthreads();
    return sh[0];
}

// ---------------- RMSNorm (in place) ----------------
__global__ __launch_bounds__(256) void rmsnorm_kernel(
    float* __restrict__ x, const float* __restrict__ w, int W, int stride)
{
    float* row = x + (long long)blockIdx.x * stride;
    float ss = 0.0f;
    for (int i = threadIdx.x; i < W; i += blockDim.x) { float v = row[i]; ss += v * v; }
    ss = blockReduceSum(ss);
    float sc = rsqrtf(ss / (float)W + 1e-6f);
    for (int i = threadIdx.x; i < W; i += blockDim.x) row[i] = row[i] * sc * w[i];
}

// ---------------- RoPE + pack (V written transposed) ----------------
__global__ __launch_bounds__(256) void rope_pack(
    const float* __restrict__ q,   // [ROWS,3072]
    const float* __restrict__ c,   // [ROWS,576]
    const float* __restrict__ kv,  // [ROWS,4096]
    float* __restrict__ Qo,        // [B,NH,S,192]
    float* __restrict__ Ko,        // [B,NH,S,192]
    float* __restrict__ Vt)        // [B,NH,DV,S]
{
    int row = blockIdx.x;
    int b = row / SEQ, s = row % SEQ;
    int t = threadIdx.x;

    __shared__ float cs[32], sn[32], kr[64];
    if (t < 32) {
        float f = exp10f(-(float)t / 8.0f);   // 10000^(-t/32)
        float ang = (float)s * f;
        sincosf(ang, &sn[t], &cs[t]);
    }
    __syncthreads();
    if (t < 64) {
        const float* kx = c + (long long)row * 576 + 512;
        int j = t; float v;
        if (j < 32) v = kx[2 * j] * cs[j] - kx[2 * j + 1] * sn[j];
        else { int i = j - 32; v = kx[2 * i + 1] * cs[i] + kx[2 * i] * sn[i]; }
        kr[j] = v;
    }
    __syncthreads();

    const float* qrow = q + (long long)row * 3072;
    for (int idx = t; idx < NH * DQK; idx += 256) {
        int h = idx / DQK, d = idx % DQK;
        float v;
        if (d < DNOPE) v = qrow[h * DQK + d];
        else {
            int j = d - DNOPE;
            const float* qx = qrow + h * DQK + DNOPE;
            if (j < 32) v = qx[2 * j] * cs[j] - qx[2 * j + 1] * sn[j];
            else { int i = j - 32; v = qx[2 * i + 1] * cs[i] + qx[2 * i] * sn[i]; }
        }
        Qo[((long long)(b * NH + h) * SEQ + s) * DQK + d] = v;
    }

    const float* kvrow = kv + (long long)row * 4096;
    for (int idx = t; idx < NH * DQK; idx += 256) {
        int h = idx / DQK, d = idx % DQK;
        float v = (d < DNOPE) ? kvrow[h * 256 + d] : kr[d - DNOPE];
        Ko[((long long)(b * NH + h) * SEQ + s) * DQK + d] = v;
    }
    for (int idx = t; idx < NH * DV; idx += 256) {
        int h = idx / DV, d = idx % DV;
        Vt[((long long)(b * NH + h) * DV + d) * SEQ + s] = kvrow[h * 256 + DNOPE + d];
    }
}

// ---------------- causal softmax (in place, zero-fills masked tail) ----------------
__global__ __launch_bounds__(128) void softmax_causal(float* __restrict__ attn)
{
    long long r = blockIdx.x;
    int q = (int)(r % SEQ);
    float* row = attn + r * SEQ;
    int t = threadIdx.x;
    int len = q + 1;

    float vals[16];
    float mx = -INFINITY;
    #pragma unroll
    for (int it = 0; it < 16; it++) {
        int i = t + it * 128;
        float v = (i < len) ? row[i] : -INFINITY;
        vals[it] = v; mx = fmaxf(mx, v);
    }
    mx = blockReduceMax(mx);

    float sum = 0.0f;
    #pragma unroll
    for (int it = 0; it < 16; it++) {
        int i = t + it * 128;
        float e = (i < len) ? __expf(vals[it] - mx) : 0.0f;
        vals[it] = e; sum += e;
    }
    sum = blockReduceSum(sum);
    float inv = 1.0f / sum;

    #pragma unroll
    for (int it = 0; it < 16; it++) {
        int i = t + it * 128;
        row[i] = (i < len) ? vals[it] * inv : 0.0f;
    }
}

// ---------------- host launch ----------------
extern "C" void kernel_launch(void* const* d_in, const int* in_sizes, int n_in,
                              void* d_out, int out_size) {
    const float* hidden    = (const float*)d_in[0];
    const float* w_q_down  = (const float*)d_in[3];
    const float* q_norm_w  = (const float*)d_in[4];
    const float* w_q_up    = (const float*)d_in[5];
    const float* w_kv_down = (const float*)d_in[6];
    const float* kv_norm_w = (const float*)d_in[7];
    const float* w_kv_up   = (const float*)d_in[8];
    const float* w_out     = (const float*)d_in[9];
    float* outp = (float*)d_out;

    void* p;
    float *qtmp, *qbig, *c, *kv, *Q, *Kk, *Vt, *ctx, *attn_fb;
    cudaGetSymbolAddress(&p, g_qtmp);    qtmp    = (float*)p;
    cudaGetSymbolAddress(&p, g_qbig);    qbig    = (float*)p;
    cudaGetSymbolAddress(&p, g_c);       c       = (float*)p;
    cudaGetSymbolAddress(&p, g_kv);      kv      = (float*)p;
    cudaGetSymbolAddress(&p, g_Q);       Q       = (float*)p;
    cudaGetSymbolAddress(&p, g_Km);      Kk      = (float*)p;
    cudaGetSymbolAddress(&p, g_Vt);      Vt      = (float*)p;
    cudaGetSymbolAddress(&p, g_ctx);     ctx     = (float*)p;
    cudaGetSymbolAddress(&p, g_attn_fb); attn_fb = (float*)p;

    const long long OUT_ELEMS  = (long long)ROWS * HID;
    const long long ATTN_ELEMS = (long long)BATCH * NH * SEQ * SEQ;
    float* attn = ((long long)out_size >= OUT_ELEMS + ATTN_ELEMS) ? (outp + OUT_ELEMS)
                                                                  : attn_fb;

    static int smem_set = 0;
    if (!smem_set) {
        cudaFuncSetAttribute(gemm_tc, cudaFuncAttributeMaxDynamicSharedMemorySize, GSMEM_BYTES);
        smem_set = 1;
    }
    dim3 thr(256);

    // q = hidden @ w_q_down^T   [4096,1536] K=2048
    gemm_tc<<<dim3(1536/128, ROWS/128, 1), thr, GSMEM_BYTES>>>(
        hidden, w_q_down, qtmp, ROWS, 1536, HID, HID, HID, 1536,
        1, 0, 0, 0, 0, 0, 0, 1.0f, 0);
    rmsnorm_kernel<<<ROWS, 256>>>(qtmp, q_norm_w, 1536, 1536);

    // q = qn @ w_q_up^T   [4096,3072] K=1536
    gemm_tc<<<dim3(3072/128, ROWS/128, 1), thr, GSMEM_BYTES>>>(
        qtmp, w_q_up, qbig, ROWS, 3072, 1536, 1536, 1536, 3072,
        1, 0, 0, 0, 0, 0, 0, 1.0f, 0);

    // c = hidden @ w_kv_down^T   [4096,576] K=2048
    gemm_tc<<<dim3((576 + 127)/128, ROWS/128, 1), thr, GSMEM_BYTES>>>(
        hidden, w_kv_down, c, ROWS, 576, HID, HID, HID, 576,
        1, 0, 0, 0, 0, 0, 0, 1.0f, 0);
    rmsnorm_kernel<<<ROWS, 256>>>(c, kv_norm_w, 512, 576);

    // kv = ckv_n @ w_kv_up^T   [4096,4096] K=512 (A lda=576)
    gemm_tc<<<dim3(4096/128, ROWS/128, 1), thr, GSMEM_BYTES>>>(
        c, w_kv_up, kv, ROWS, 4096, 512, 576, 512, 4096,
        1, 0, 0, 0, 0, 0, 0, 1.0f, 0);

    // RoPE + pack (V transposed)
    rope_pack<<<ROWS, 256>>>(qbig, c, kv, Q, Kk, Vt);

    // scores = Q K^T / sqrt(192), causal tile-skip, batched over 32 (b,h)
    float alpha = rsqrtf((float)DQK);
    gemm_tc<<<dim3(SEQ/128, SEQ/128, BATCH*NH), thr, GSMEM_BYTES>>>(
        Q, Kk, attn, SEQ, SEQ, DQK, DQK, DQK, SEQ,
        1, (long long)SEQ*DQK, 0,
        (long long)SEQ*DQK, 0,
        (long long)SEQ*SEQ, 0,
        alpha, 1);

    // softmax (zero-fills masked region)
    softmax_causal<<<BATCH*NH*SEQ, 128>>>(attn);

    // ctx = attn @ V = attn @ (Vt)^T : NT with B=Vt, causal K-truncation
    gemm_tc<<<dim3(1, SEQ/128, BATCH*NH), thr, GSMEM_BYTES>>>(
        attn, Vt, ctx, SEQ, DV, SEQ, SEQ, SEQ, NH*DV,
        NH,
        (long long)NH*SEQ*SEQ, (long long)SEQ*SEQ,
        (long long)NH*DV*SEQ,  (long long)DV*SEQ,
        (long long)SEQ*NH*DV,  (long long)DV,
        1.0f, 2);

    // out = ctx @ w_out^T   [4096,2048] K=2048
    gemm_tc<<<dim3(HID/128, ROWS/128, 1), thr, GSMEM_BYTES>>>(
        ctx, w_out, outp, ROWS, HID, NH*DV, NH*DV, NH*DV, HID,
        1, 0, 0, 0, 0, 0, 0, 1.0f, 0);
}

// round 5
// speedup vs baseline: 3.3379x; 1.1622x over previous
#include <cuda_runtime.h>
#include <cuda_fp16.h>
#include <math.h>
#include <stdint.h>

#define BATCH 2
#define SEQ   2048
#define HID   2048
#define NH    16
#define DNOPE 128
#define DROPE 64
#define DV    128
#define DQK   192
#define LORA  512
#define ROWS  (BATCH*SEQ)   // 4096

// ---------------- scratch (static device memory; no allocations) ----------------
__device__ float g_qtmp[(size_t)ROWS*1536];
__device__ float g_qbig[(size_t)ROWS*3072];
__device__ float g_c   [(size_t)ROWS*576];
__device__ float g_kv  [(size_t)ROWS*4096];
__device__ float g_Q   [(size_t)BATCH*NH*SEQ*DQK];
__device__ float g_Km  [(size_t)BATCH*NH*SEQ*DQK];
__device__ float g_Vt  [(size_t)BATCH*NH*DV*SEQ];     // V transposed per (b,h): [DV][SEQ]
__device__ float g_ctx [(size_t)ROWS*NH*DV];
__device__ float g_attn_fb[(size_t)BATCH*NH*SEQ*SEQ];

__device__ __forceinline__ uint32_t f2h2(float a, float b) {
    __half2 h = __floats2half2_rn(a, b);
    return *(uint32_t*)&h;
}

#define MMA_F16(ac, ar, br)                                                       \
    asm volatile("mma.sync.aligned.m16n8k16.row.col.f32.f16.f16.f32 "             \
                 "{%0,%1,%2,%3}, {%4,%5,%6,%7}, {%8,%9}, {%0,%1,%2,%3};"          \
                 : "+f"((ac)[0]), "+f"((ac)[1]), "+f"((ac)[2]), "+f"((ac)[3])     \
                 : "r"((ar)[0]), "r"((ar)[1]), "r"((ar)[2]), "r"((ar)[3]),        \
                   "r"((br)[0]), "r"((br)[1]))

// ---------------- fp16 mma.sync NT GEMM ----------------
// C[m,n] = alpha * sum_k A[m,k] * B[n,k]  (A,B fp32 in gmem; converted to fp16
// at staging with rn rounding; fp32 accumulate)
// CTA 128 x (NI*32), BK=32, 8 warps; warp tile 64 x (NI*8).
// SMEM: half2 words, 16 words/row, kw XOR-swizzled by 2*(row&7) -> conflict-free
// fragment LDS.32; staging pairs stay adjacent (XOR value even).
// mode: 0 dense, 1 causal tile-skip, 2 causal K-truncation.
template<int NI>
__global__ __launch_bounds__(256) void gemm_h(
    const float* __restrict__ A, const float* __restrict__ B, float* __restrict__ C,
    int M, int N, int K, int lda, int ldb, int ldc,
    int zdiv, long long sA1, long long sA2,
    long long sB1, long long sB2, long long sC1, long long sC2,
    float alpha, int mode)
{
    constexpr int BN = NI * 32;
    constexpr int AW = 2048;        // A words per buffer (128 rows x 16 half2)
    constexpr int BW = BN * 16;     // B words per buffer
    constexpr int BUF = AW + BW;

    int z  = blockIdx.z;
    int m0 = blockIdx.y * 128;
    int n0 = blockIdx.x * BN;
    if (mode == 1 && n0 > m0 + 127) return;

    const float* Ab = A + (long long)(z / zdiv) * sA1 + (long long)(z % zdiv) * sA2;
    const float* Bb = B + (long long)(z / zdiv) * sB1 + (long long)(z % zdiv) * sB2;
    float*       Cb = C + (long long)(z / zdiv) * sC1 + (long long)(z % zdiv) * sC2;

    extern __shared__ uint32_t sm[];

    int t    = threadIdx.x;
    int lane = t & 31;
    int wid  = t >> 5;
    int g    = lane >> 2;       // groupID 0..7
    int t4   = lane & 3;        // thread in group 0..3
    int wm   = wid >> 2;        // 0..1 -> M offset wm*64
    int wn   = wid & 3;         // 0..3 -> N offset wn*(NI*8)

    int kEnd = K;
    if (mode == 2) { int ke = m0 + 128; kEnd = (ke < K) ? ke : K; }
    int nk = kEnd >> 5;         // BK = 32

    float acc[4][NI][4];
    #pragma unroll
    for (int mi = 0; mi < 4; mi++)
        #pragma unroll
        for (int ni = 0; ni < NI; ni++)
            #pragma unroll
            for (int r = 0; r < 4; r++) acc[mi][ni][r] = 0.0f;

    int srow = t >> 3;          // staging: 8 float4 per row
    int sc4  = t & 7;

    uint2 ra[4], rb[NI];

    // ---- load + convert chunk into regs (half2 pairs)
    auto ldg_chunk = [&](int k0) {
        #pragma unroll
        for (int i = 0; i < 4; i++) {
            int row = srow + i * 32;
            float4 v = *(const float4*)(Ab + (size_t)(m0 + row) * lda + k0 + sc4 * 4);
            ra[i] = make_uint2(f2h2(v.x, v.y), f2h2(v.z, v.w));
        }
        #pragma unroll
        for (int i = 0; i < NI; i++) {
            int row = srow + i * 32;
            if (n0 + row < N) {
                float4 v = *(const float4*)(Bb + (size_t)(n0 + row) * ldb + k0 + sc4 * 4);
                rb[i] = make_uint2(f2h2(v.x, v.y), f2h2(v.z, v.w));
            } else {
                rb[i] = make_uint2(0u, 0u);
            }
        }
    };
    // ---- store regs into buffer b (swizzled)
    auto sts_chunk = [&](int b) {
        uint32_t* A_ = sm + b * BUF;
        uint32_t* B_ = A_ + AW;
        #pragma unroll
        for (int i = 0; i < 4; i++) {
            int row = srow + i * 32;
            int w   = row * 16 + ((sc4 * 2) ^ ((row & 7) * 2));
            *(uint2*)(A_ + w) = ra[i];
        }
        #pragma unroll
        for (int i = 0; i < NI; i++) {
            int row = srow + i * 32;
            int w   = row * 16 + ((sc4 * 2) ^ ((row & 7) * 2));
            *(uint2*)(B_ + w) = rb[i];
        }
    };
    // ---- mma over buffer b
    auto mma_chunk = [&](int b) {
        const uint32_t* A_ = sm + b * BUF;
        const uint32_t* B_ = A_ + AW;
        int sxg = 2 * g;
        #pragma unroll
        for (int ks = 0; ks < 2; ks++) {
            int kw0 = (ks * 8 + t4) ^ sxg;
            int kw1 = (ks * 8 + t4 + 4) ^ sxg;
            uint32_t af[4][4], bf[NI][2];
            #pragma unroll
            for (int mi = 0; mi < 4; mi++) {
                int r0 = wm * 64 + mi * 16 + g;
                af[mi][0] = A_[r0 * 16 + kw0];
                af[mi][1] = A_[(r0 + 8) * 16 + kw0];
                af[mi][2] = A_[r0 * 16 + kw1];
                af[mi][3] = A_[(r0 + 8) * 16 + kw1];
            }
            #pragma unroll
            for (int ni = 0; ni < NI; ni++) {
                int n = wn * (NI * 8) + ni * 8 + g;
                bf[ni][0] = B_[n * 16 + kw0];
                bf[ni][1] = B_[n * 16 + kw1];
            }
            #pragma unroll
            for (int mi = 0; mi < 4; mi++)
                #pragma unroll
                for (int ni = 0; ni < NI; ni++)
                    MMA_F16(acc[mi][ni], af[mi], bf[ni]);
        }
    };

    ldg_chunk(0);
    sts_chunk(0);
    __syncthreads();

    for (int kt = 0; kt < nk; kt++) {
        int b = kt & 1;
        if (kt + 1 < nk) ldg_chunk((kt + 1) << 5);
        mma_chunk(b);
        if (kt + 1 < nk) sts_chunk(b ^ 1);
        __syncthreads();
    }

    // epilogue
    #pragma unroll
    for (int mi = 0; mi < 4; mi++) {
        int row = m0 + wm * 64 + mi * 16 + g;
        #pragma unroll
        for (int ni = 0; ni < NI; ni++) {
            int col = n0 + wn * (NI * 8) + ni * 8 + 2 * t4;
            if (col < N) {
                float2 v0 = make_float2(alpha * acc[mi][ni][0], alpha * acc[mi][ni][1]);
                float2 v1 = make_float2(alpha * acc[mi][ni][2], alpha * acc[mi][ni][3]);
                *(float2*)(Cb + (size_t)row * ldc + col)       = v0;
                *(float2*)(Cb + (size_t)(row + 8) * ldc + col) = v1;
            }
        }
    }
}

// ---------------- block reductions ----------------
__device__ __forceinline__ float blockReduceSum(float v) {
    __shared__ float sh[32];
    int lane = threadIdx.x & 31, w = threadIdx.x >> 5;
    #pragma unroll
    for (int o = 16; o > 0; o >>= 1) v += __shfl_xor_sync(0xffffffffu, v, o);
    __syncthreads();
    if (lane == 0) sh[w] = v;
    __syncthreads();
    int nw = (blockDim.x + 31) >> 5;
    float r = (threadIdx.x < nw) ? sh[threadIdx.x] : 0.0f;
    if (w == 0) {
        #pragma unroll
        for (int o = 16; o > 0; o >>= 1) r += __shfl_xor_sync(0xffffffffu, r, o);
        if (lane == 0) sh[0] = r;
    }
    __syncthreads();
    return sh[0];
}
__device__ __forceinline__ float blockReduceMax(float v) {
    __shared__ float sh[32];
    int lane = threadIdx.x & 31, w = threadIdx.x >> 5;
    #pragma unroll
    for (int o = 16; o > 0; o >>= 1) v = fmaxf(v, __shfl_xor_sync(0xffffffffu, v, o));
    __syncthreads();
    if (lane == 0) sh[w] = v;
    __syncthreads();
    int nw = (blockDim.x + 31) >> 5;
    float r = (threadIdx.x < nw) ? sh[threadIdx.x] : -INFINITY;
    if (w == 0) {
        #pragma unroll
        for (int o = 16; o > 0; o >>= 1) r = fmaxf(r, __shfl_xor_sync(0xffffffffu, r, o));
        if (lane == 0) sh[0] = r;
    }
    __syncthreads();
    return sh[0];
}

// ---------------- RMSNorm (in place) ----------------
__global__ __launch_bounds__(256) void rmsnorm_kernel(
    float* __restrict__ x, const float* __restrict__ w, int W, int stride)
{
    float* row = x + (long long)blockIdx.x * stride;
    float ss = 0.0f;
    for (int i = threadIdx.x; i < W; i += blockDim.x) { float v = row[i]; ss += v * v; }
    ss = blockReduceSum(ss);
    float sc = rsqrtf(ss / (float)W + 1e-6f);
    for (int i = threadIdx.x; i < W; i += blockDim.x) row[i] = row[i] * sc * w[i];
}

// ---------------- RoPE + pack (V written transposed) ----------------
__global__ __launch_bounds__(256) void rope_pack(
    const float* __restrict__ q,   // [ROWS,3072]
    const float* __restrict__ c,   // [ROWS,576]
    const float* __restrict__ kv,  // [ROWS,4096]
    float* __restrict__ Qo,        // [B,NH,S,192]
    float* __restrict__ Ko,        // [B,NH,S,192]
    float* __restrict__ Vt)        // [B,NH,DV,S]
{
    int row = blockIdx.x;
    int b = row / SEQ, s = row % SEQ;
    int t = threadIdx.x;

    __shared__ float cs[32], sn[32], kr[64];
    if (t < 32) {
        float f = exp10f(-(float)t / 8.0f);   // 10000^(-t/32)
        float ang = (float)s * f;
        sincosf(ang, &sn[t], &cs[t]);
    }
    __syncthreads();
    if (t < 64) {
        const float* kx = c + (long long)row * 576 + 512;
        int j = t; float v;
        if (j < 32) v = kx[2 * j] * cs[j] - kx[2 * j + 1] * sn[j];
        else { int i = j - 32; v = kx[2 * i + 1] * cs[i] + kx[2 * i] * sn[i]; }
        kr[j] = v;
    }
    __syncthreads();

    const float* qrow = q + (long long)row * 3072;
    for (int idx = t; idx < NH * DQK; idx += 256) {
        int h = idx / DQK, d = idx % DQK;
        float v;
        if (d < DNOPE) v = qrow[h * DQK + d];
        else {
            int j = d - DNOPE;
            const float* qx = qrow + h * DQK + DNOPE;
            if (j < 32) v = qx[2 * j] * cs[j] - qx[2 * j + 1] * sn[j];
            else { int i = j - 32; v = qx[2 * i + 1] * cs[i] + qx[2 * i] * sn[i]; }
        }
        Qo[((long long)(b * NH + h) * SEQ + s) * DQK + d] = v;
    }

    const float* kvrow = kv + (long long)row * 4096;
    for (int idx = t; idx < NH * DQK; idx += 256) {
        int h = idx / DQK, d = idx % DQK;
        float v = (d < DNOPE) ? kvrow[h * 256 + d] : kr[d - DNOPE];
        Ko[((long long)(b * NH + h) * SEQ + s) * DQK + d] = v;
    }
    for (int idx = t; idx < NH * DV; idx += 256) {
        int h = idx / DV, d = idx % DV;
        Vt[((long long)(b * NH + h) * DV + d) * SEQ + s] = kvrow[h * 256 + DNOPE + d];
    }
}

// ---------------- causal softmax (in place, zero-fills masked tail) ----------------
__global__ __launch_bounds__(128) void softmax_causal(float* __restrict__ attn)
{
    long long r = blockIdx.x;
    int q = (int)(r % SEQ);
    float* row = attn + r * SEQ;
    int t = threadIdx.x;
    int len = q + 1;

    float vals[16];
    float mx = -INFINITY;
    #pragma unroll
    for (int it = 0; it < 16; it++) {
        int i = t + it * 128;
        float v = (i < len) ? row[i] : -INFINITY;
        vals[it] = v; mx = fmaxf(mx, v);
    }
    mx = blockReduceMax(mx);

    float sum = 0.0f;
    #pragma unroll
    for (int it = 0; it < 16; it++) {
        int i = t + it * 128;
        float e = (i < len) ? __expf(vals[it] - mx) : 0.0f;
        vals[it] = e; sum += e;
    }
    sum = blockReduceSum(sum);
    float inv = 1.0f / sum;

    #pragma unroll
    for (int it = 0; it < 16; it++) {
        int i = t + it * 128;
        row[i] = (i < len) ? vals[it] * inv : 0.0f;
    }
}

// ---------------- host launch ----------------
#define SMEM_NI8 ((2048 + 256*16) * 2 * 4)   // 49152 B
#define SMEM_NI4 ((2048 + 128*16) * 2 * 4)   // 32768 B

extern "C" void kernel_launch(void* const* d_in, const int* in_sizes, int n_in,
                              void* d_out, int out_size) {
    const float* hidden    = (const float*)d_in[0];
    const float* w_q_down  = (const float*)d_in[3];
    const float* q_norm_w  = (const float*)d_in[4];
    const float* w_q_up    = (const float*)d_in[5];
    const float* w_kv_down = (const float*)d_in[6];
    const float* kv_norm_w = (const float*)d_in[7];
    const float* w_kv_up   = (const float*)d_in[8];
    const float* w_out     = (const float*)d_in[9];
    float* outp = (float*)d_out;

    void* p;
    float *qtmp, *qbig, *c, *kv, *Q, *Kk, *Vt, *ctx, *attn_fb;
    cudaGetSymbolAddress(&p, g_qtmp);    qtmp    = (float*)p;
    cudaGetSymbolAddress(&p, g_qbig);    qbig    = (float*)p;
    cudaGetSymbolAddress(&p, g_c);       c       = (float*)p;
    cudaGetSymbolAddress(&p, g_kv);      kv      = (float*)p;
    cudaGetSymbolAddress(&p, g_Q);       Q       = (float*)p;
    cudaGetSymbolAddress(&p, g_Km);      Kk      = (float*)p;
    cudaGetSymbolAddress(&p, g_Vt);      Vt      = (float*)p;
    cudaGetSymbolAddress(&p, g_ctx);     ctx     = (float*)p;
    cudaGetSymbolAddress(&p, g_attn_fb); attn_fb = (float*)p;

    const long long OUT_ELEMS  = (long long)ROWS * HID;
    const long long ATTN_ELEMS = (long long)BATCH * NH * SEQ * SEQ;
    float* attn = ((long long)out_size >= OUT_ELEMS + ATTN_ELEMS) ? (outp + OUT_ELEMS)
                                                                  : attn_fb;

    static int inited = 0;
    if (!inited) {
        cudaFuncSetAttribute(gemm_h<8>, cudaFuncAttributeMaxDynamicSharedMemorySize, SMEM_NI8);
        cudaFuncSetAttribute(gemm_h<4>, cudaFuncAttributeMaxDynamicSharedMemorySize, SMEM_NI4);
        inited = 1;
    }
    dim3 thr(256);

    // q = hidden @ w_q_down^T   [4096,1536] K=2048
    gemm_h<8><<<dim3(1536/256, ROWS/128, 1), thr, SMEM_NI8>>>(
        hidden, w_q_down, qtmp, ROWS, 1536, HID, HID, HID, 1536,
        1, 0, 0, 0, 0, 0, 0, 1.0f, 0);
    rmsnorm_kernel<<<ROWS, 256>>>(qtmp, q_norm_w, 1536, 1536);

    // q = qn @ w_q_up^T   [4096,3072] K=1536
    gemm_h<8><<<dim3(3072/256, ROWS/128, 1), thr, SMEM_NI8>>>(
        qtmp, w_q_up, qbig, ROWS, 3072, 1536, 1536, 1536, 3072,
        1, 0, 0, 0, 0, 0, 0, 1.0f, 0);

    // c = hidden @ w_kv_down^T   [4096,576] K=2048  (small N -> 128-wide tiles)
    gemm_h<4><<<dim3((576 + 127)/128, ROWS/128, 1), thr, SMEM_NI4>>>(
        hidden, w_kv_down, c, ROWS, 576, HID, HID, HID, 576,
        1, 0, 0, 0, 0, 0, 0, 1.0f, 0);
    rmsnorm_kernel<<<ROWS, 256>>>(c, kv_norm_w, 512, 576);

    // kv = ckv_n @ w_kv_up^T   [4096,4096] K=512 (A lda=576)
    gemm_h<8><<<dim3(4096/256, ROWS/128, 1), thr, SMEM_NI8>>>(
        c, w_kv_up, kv, ROWS, 4096, 512, 576, 512, 4096,
        1, 0, 0, 0, 0, 0, 0, 1.0f, 0);

    // RoPE + pack (V transposed)
    rope_pack<<<ROWS, 256>>>(qbig, c, kv, Q, Kk, Vt);

    // scores = Q K^T / sqrt(192), causal tile-skip, batched over 32 (b,h)
    float alpha = rsqrtf((float)DQK);
    gemm_h<8><<<dim3(SEQ/256, SEQ/128, BATCH*NH), thr, SMEM_NI8>>>(
        Q, Kk, attn, SEQ, SEQ, DQK, DQK, DQK, SEQ,
        1, (long long)SEQ*DQK, 0,
        (long long)SEQ*DQK, 0,
        (long long)SEQ*SEQ, 0,
        alpha, 1);

    // softmax (zero-fills masked region)
    softmax_causal<<<BATCH*NH*SEQ, 128>>>(attn);

    // ctx = attn @ V = attn @ (Vt)^T : NT with B=Vt, causal K-truncation
    gemm_h<4><<<dim3(1, SEQ/128, BATCH*NH), thr, SMEM_NI4>>>(
        attn, Vt, ctx, SEQ, DV, SEQ, SEQ, SEQ, NH*DV,
        NH,
        (long long)NH*SEQ*SEQ, (long long)SEQ*SEQ,
        (long long)NH*DV*SEQ,  (long long)DV*SEQ,
        (long long)SEQ*NH*DV,  (long long)DV,
        1.0f, 2);

    // out = ctx @ w_out^T   [4096,2048] K=2048
    gemm_h<8><<<dim3(HID/256, ROWS/128, 1), thr, SMEM_NI8>>>(
        ctx, w_out, outp, ROWS, HID, NH*DV, NH*DV, NH*DV, HID,
        1, 0, 0, 0, 0, 0, 0, 1.0f, 0);
}

// round 6
// speedup vs baseline: 4.6106x; 1.3813x over previous
#include <cuda_runtime.h>
#include <cuda_fp16.h>
#include <math.h>
#include <stdint.h>

#define BATCH 2
#define SEQ   2048
#define HID   2048
#define NH    16
#define DNOPE 128
#define DROPE 64
#define DV    128
#define DQK   192
#define LORA  512
#define ROWS  (BATCH*SEQ)   // 4096
#define NS    4             // cp.async pipeline stages

// ---------------- scratch (static device memory; no allocations) ----------------
__device__ __half g_hidden16[(size_t)ROWS*HID];
__device__ __half g_wqd16 [(size_t)1536*HID];
__device__ __half g_wqup16[(size_t)3072*1536];
__device__ __half g_wkvd16[(size_t)576*HID];
__device__ __half g_wkvup16[(size_t)4096*512];
__device__ __half g_wout16[(size_t)HID*HID];
__device__ __half g_qtmp16[(size_t)ROWS*1536];
__device__ __half g_qbig16[(size_t)ROWS*3072];
__device__ __half g_c16   [(size_t)ROWS*576];
__device__ __half g_kv16  [(size_t)ROWS*4096];
__device__ __half g_Q16   [(size_t)BATCH*NH*SEQ*DQK];
__device__ __half g_K16   [(size_t)BATCH*NH*SEQ*DQK];
__device__ __half g_Vt16  [(size_t)BATCH*NH*DV*SEQ];   // V transposed per (b,h)
__device__ __half g_ctx16 [(size_t)ROWS*NH*DV];
__device__ __half g_attn16[(size_t)BATCH*NH*SEQ*SEQ];  // fp16 copy of attn for attn@V
__device__ float  g_attn_fb[(size_t)BATCH*NH*SEQ*SEQ]; // fallback fp32 attn

__device__ __forceinline__ uint32_t smem_u32(const void* p) {
    uint32_t a;
    asm("{ .reg .u64 t; cvta.to.shared.u64 t, %1; cvt.u32.u64 %0, t; }" : "=r"(a) : "l"(p));
    return a;
}

#define MMA_F16(ac, ar, br)                                                       \
    asm volatile("mma.sync.aligned.m16n8k16.row.col.f32.f16.f16.f32 "             \
                 "{%0,%1,%2,%3}, {%4,%5,%6,%7}, {%8,%9}, {%0,%1,%2,%3};"          \
                 : "+f"((ac)[0]), "+f"((ac)[1]), "+f"((ac)[2]), "+f"((ac)[3])     \
                 : "r"((ar)[0]), "r"((ar)[1]), "r"((ar)[2]), "r"((ar)[3]),        \
                   "r"((br)[0]), "r"((br)[1]))

// ---------------- fp32 -> fp16 conversion ----------------
__global__ __launch_bounds__(256) void f2h_kernel(
    const float4* __restrict__ src, uint2* __restrict__ dst, int n4)
{
    int i = blockIdx.x * blockDim.x + threadIdx.x;
    if (i < n4) {
        float4 v = src[i];
        __half2 a = __floats2half2_rn(v.x, v.y);
        __half2 b = __floats2half2_rn(v.z, v.w);
        dst[i] = make_uint2(*(uint32_t*)&a, *(uint32_t*)&b);
    }
}

// ---------------- fp16 mma.sync NT GEMM, cp.async 4-stage pipeline ----------------
// C[m,n] = alpha * sum_k A[m,k]*B[n,k] ; A,B fp16 in gmem, fp32 accumulate.
// CTA 128x128, BK=32, 8 warps, warp tile 64x32 (4x4 of m16n8k16).
// SMEM per stage: A 8KB + B 8KB, rows of 16 uint32 words, 8B chunks XOR-swizzled
// by (row&7)*2 words -> conflict-free LDS.32 fragment loads (verified R4/R5).
// mode: 0 dense, 1 causal tile-skip, 2 causal K-truncation. outhalf: C dtype.
#define GSMEM_BYTES (NS * 16384)

__global__ __launch_bounds__(256, 2) void gemm_h16(
    const __half* __restrict__ A, const __half* __restrict__ B, void* __restrict__ Cv,
    int M, int N, int K, int lda, int ldb, int ldc,
    int zdiv, long long sA1, long long sA2,
    long long sB1, long long sB2, long long sC1, long long sC2,
    float alpha, int mode, int outhalf)
{
    int z  = blockIdx.z;
    int m0 = blockIdx.y * 128;
    int n0 = blockIdx.x * 128;
    if (mode == 1 && n0 > m0) return;

    const __half* Ab = A + (long long)(z / zdiv) * sA1 + (long long)(z % zdiv) * sA2;
    const __half* Bb = B + (long long)(z / zdiv) * sB1 + (long long)(z % zdiv) * sB2;
    long long coff = (long long)(z / zdiv) * sC1 + (long long)(z % zdiv) * sC2;

    extern __shared__ uint32_t sm[];
    uint32_t smb = smem_u32(sm);

    int t    = threadIdx.x;
    int lane = t & 31;
    int wid  = t >> 5;
    int g    = lane >> 2;
    int t4   = lane & 3;
    int wm   = wid >> 2;        // 0..1
    int wn   = wid & 3;         // 0..3

    int kEnd = K;
    if (mode == 2) { int ke = m0 + 128; kEnd = (ke < K) ? ke : K; }
    int nk = kEnd >> 5;

    float acc[4][4][4];
    #pragma unroll
    for (int mi = 0; mi < 4; mi++)
        #pragma unroll
        for (int ni = 0; ni < 4; ni++)
            #pragma unroll
            for (int r = 0; r < 4; r++) acc[mi][ni][r] = 0.0f;

    int srow = t >> 3;          // staging: row = srow + i*32 ; 8B chunk = t&7
    int sch  = t & 7;

    // ---- issue one K-chunk into stage st via cp.async (8B granules)
    auto issue = [&](int kt, int st) {
        int k0 = kt << 5;
        uint32_t sA = smb + st * 16384;
        uint32_t sB = sA + 8192;
        #pragma unroll
        for (int i = 0; i < 4; i++) {
            int row = srow + i * 32;
            uint32_t woff = (uint32_t)(row * 16 + ((sch * 2) ^ ((row & 7) * 2))) * 4;
            const __half* ga = Ab + (size_t)(m0 + row) * lda + k0 + sch * 4;
            asm volatile("cp.async.ca.shared.global [%0], [%1], 8;"
                         :: "r"(sA + woff), "l"(ga));
            int brow = n0 + row;
            const __half* gb = Bb + (size_t)(brow < N ? brow : 0) * ldb + k0 + sch * 4;
            int ssz = (brow < N) ? 8 : 0;
            asm volatile("cp.async.ca.shared.global [%0], [%1], 8, %2;"
                         :: "r"(sB + woff), "l"(gb), "r"(ssz));
        }
    };

    // ---- mma over stage st
    auto mma_chunk = [&](int st) {
        const uint32_t* A_ = sm + st * 4096;
        const uint32_t* B_ = A_ + 2048;
        int sxg = 2 * g;
        #pragma unroll
        for (int ks = 0; ks < 2; ks++) {
            int kw0 = (ks * 8 + t4) ^ sxg;
            int kw1 = (ks * 8 + t4 + 4) ^ sxg;
            uint32_t af[4][4], bf[4][2];
            #pragma unroll
            for (int mi = 0; mi < 4; mi++) {
                int r0 = wm * 64 + mi * 16 + g;
                af[mi][0] = A_[r0 * 16 + kw0];
                af[mi][1] = A_[(r0 + 8) * 16 + kw0];
                af[mi][2] = A_[r0 * 16 + kw1];
                af[mi][3] = A_[(r0 + 8) * 16 + kw1];
            }
            #pragma unroll
            for (int ni = 0; ni < 4; ni++) {
                int n = wn * 32 + ni * 8 + g;
                bf[ni][0] = B_[n * 16 + kw0];
                bf[ni][1] = B_[n * 16 + kw1];
            }
            #pragma unroll
            for (int mi = 0; mi < 4; mi++)
                #pragma unroll
                for (int ni = 0; ni < 4; ni++)
                    MMA_F16(acc[mi][ni], af[mi], bf[ni]);
        }
    };

    // prologue: NS-1 stages in flight
    #pragma unroll
    for (int s = 0; s < NS - 1; s++) {
        if (s < nk) issue(s, s);
        asm volatile("cp.async.commit_group;" ::: "memory");
    }

    for (int kt = 0; kt < nk; kt++) {
        int nxt = kt + NS - 1;
        if (nxt < nk) issue(nxt, nxt & (NS - 1));
        asm volatile("cp.async.commit_group;" ::: "memory");
        asm volatile("cp.async.wait_group %0;" :: "n"(NS - 2) : "memory");
        __syncthreads();
        mma_chunk(kt & (NS - 1));
        __syncthreads();
    }

    // epilogue
    #pragma unroll
    for (int mi = 0; mi < 4; mi++) {
        int row = m0 + wm * 64 + mi * 16 + g;
        #pragma unroll
        for (int ni = 0; ni < 4; ni++) {
            int col = n0 + wn * 32 + ni * 8 + 2 * t4;
            if (col < N) {
                if (outhalf) {
                    __half* Cb = (__half*)Cv + coff;
                    __half2 h0 = __floats2half2_rn(alpha * acc[mi][ni][0], alpha * acc[mi][ni][1]);
                    __half2 h1 = __floats2half2_rn(alpha * acc[mi][ni][2], alpha * acc[mi][ni][3]);
                    *(__half2*)(Cb + (size_t)row * ldc + col)       = h0;
                    *(__half2*)(Cb + (size_t)(row + 8) * ldc + col) = h1;
                } else {
                    float* Cb = (float*)Cv + coff;
                    float2 v0 = make_float2(alpha * acc[mi][ni][0], alpha * acc[mi][ni][1]);
                    float2 v1 = make_float2(alpha * acc[mi][ni][2], alpha * acc[mi][ni][3]);
                    *(float2*)(Cb + (size_t)row * ldc + col)       = v0;
                    *(float2*)(Cb + (size_t)(row + 8) * ldc + col) = v1;
                }
            }
        }
    }
}

// ---------------- block reductions ----------------
__device__ __forceinline__ float blockReduceSum(float v) {
    __shared__ float sh[32];
    int lane = threadIdx.x & 31, w = threadIdx.x >> 5;
    #pragma unroll
    for (int o = 16; o > 0; o >>= 1) v += __shfl_xor_sync(0xffffffffu, v, o);
    __syncthreads();
    if (lane == 0) sh[w] = v;
    __syncthreads();
    int nw = (blockDim.x + 31) >> 5;
    float r = (threadIdx.x < nw) ? sh[threadIdx.x] : 0.0f;
    if (w == 0) {
        #pragma unroll
        for (int o = 16; o > 0; o >>= 1) r += __shfl_xor_sync(0xffffffffu, r, o);
        if (lane == 0) sh[0] = r;
    }
    __syncthreads();
    return sh[0];
}
__device__ __forceinline__ float blockReduceMax(float v) {
    __shared__ float sh[32];
    int lane = threadIdx.x & 31, w = threadIdx.x >> 5;
    #pragma unroll
    for (int o = 16; o > 0; o >>= 1) v = fmaxf(v, __shfl_xor_sync(0xffffffffu, v, o));
    __syncthreads();
    if (lane == 0) sh[w] = v;
    __syncthreads();
    int nw = (blockDim.x + 31) >> 5;
    float r = (threadIdx.x < nw) ? sh[threadIdx.x] : -INFINITY;
    if (w == 0) {
        #pragma unroll
        for (int o = 16; o > 0; o >>= 1) r = fmaxf(r, __shfl_xor_sync(0xffffffffu, r, o));
        if (lane == 0) sh[0] = r;
    }
    __syncthreads();
    return sh[0];
}

// ---------------- RMSNorm fp16 (in place) ----------------
__global__ __launch_bounds__(256) void rmsnorm16(
    __half* __restrict__ x, const float* __restrict__ w, int W, int stride)
{
    __half* row = x + (long long)blockIdx.x * stride;
    float ss = 0.0f;
    for (int i = threadIdx.x; i < W; i += blockDim.x) {
        float v = __half2float(row[i]); ss += v * v;
    }
    ss = blockReduceSum(ss);
    float sc = rsqrtf(ss / (float)W + 1e-6f);
    for (int i = threadIdx.x; i < W; i += blockDim.x)
        row[i] = __float2half(__half2float(row[i]) * sc * w[i]);
}

// ---------------- RoPE + pack fp16 (V written transposed) ----------------
__global__ __launch_bounds__(256) void rope_pack16(
    const __half* __restrict__ q,   // [ROWS,3072]
    const __half* __restrict__ c,   // [ROWS,576]
    const __half* __restrict__ kv,  // [ROWS,4096]
    __half* __restrict__ Qo,        // [B,NH,S,192]
    __half* __restrict__ Ko,        // [B,NH,S,192]
    __half* __restrict__ Vt)        // [B,NH,DV,S]
{
    int row = blockIdx.x;
    int b = row / SEQ, s = row % SEQ;
    int t = threadIdx.x;

    __shared__ float cs[32], sn[32];
    __shared__ __half kr[64];
    if (t < 32) {
        float f = exp10f(-(float)t / 8.0f);   // 10000^(-t/32)
        float ang = (float)s * f;
        sincosf(ang, &sn[t], &cs[t]);
    }
    __syncthreads();
    if (t < 64) {
        const __half* kx = c + (long long)row * 576 + 512;
        int j = t; float v;
        if (j < 32) v = __half2float(kx[2*j]) * cs[j] - __half2float(kx[2*j+1]) * sn[j];
        else { int i = j - 32; v = __half2float(kx[2*i+1]) * cs[i] + __half2float(kx[2*i]) * sn[i]; }
        kr[j] = __float2half(v);
    }
    __syncthreads();

    const __half* qrow = q + (long long)row * 3072;
    for (int idx = t; idx < NH * DQK; idx += 256) {
        int h = idx / DQK, d = idx % DQK;
        __half v;
        if (d < DNOPE) v = qrow[h * DQK + d];
        else {
            int j = d - DNOPE;
            const __half* qx = qrow + h * DQK + DNOPE;
            float vv;
            if (j < 32) vv = __half2float(qx[2*j]) * cs[j] - __half2float(qx[2*j+1]) * sn[j];
            else { int i = j - 32; vv = __half2float(qx[2*i+1]) * cs[i] + __half2float(qx[2*i]) * sn[i]; }
            v = __float2half(vv);
        }
        Qo[((long long)(b * NH + h) * SEQ + s) * DQK + d] = v;
    }

    const __half* kvrow = kv + (long long)row * 4096;
    for (int idx = t; idx < NH * DQK; idx += 256) {
        int h = idx / DQK, d = idx % DQK;
        __half v = (d < DNOPE) ? kvrow[h * 256 + d] : kr[d - DNOPE];
        Ko[((long long)(b * NH + h) * SEQ + s) * DQK + d] = v;
    }
    for (int idx = t; idx < NH * DV; idx += 256) {
        int h = idx / DV, d = idx % DV;
        Vt[((long long)(b * NH + h) * DV + d) * SEQ + s] = kvrow[h * 256 + DNOPE + d];
    }
}

// ---------------- causal softmax: fp32 in/out + fp16 copy ----------------
__global__ __launch_bounds__(128) void softmax_causal(
    float* __restrict__ attn, __half* __restrict__ attn16)
{
    long long r = blockIdx.x;
    int q = (int)(r % SEQ);
    float*  row  = attn   + r * SEQ;
    __half* row16 = attn16 + r * SEQ;
    int t = threadIdx.x;
    int len = q + 1;

    float vals[16];
    float mx = -INFINITY;
    #pragma unroll
    for (int it = 0; it < 16; it++) {
        int i = t + it * 128;
        float v = (i < len) ? row[i] : -INFINITY;
        vals[it] = v; mx = fmaxf(mx, v);
    }
    mx = blockReduceMax(mx);

    float sum = 0.0f;
    #pragma unroll
    for (int it = 0; it < 16; it++) {
        int i = t + it * 128;
        float e = (i < len) ? __expf(vals[it] - mx) : 0.0f;
        vals[it] = e; sum += e;
    }
    sum = blockReduceSum(sum);
    float inv = 1.0f / sum;

    #pragma unroll
    for (int it = 0; it < 16; it++) {
        int i = t + it * 128;
        float o = (i < len) ? vals[it] * inv : 0.0f;
        row[i]   = o;
        row16[i] = __float2half(o);
    }
}

// ---------------- host launch ----------------
static inline void conv(const float* s, __half* d, long long n) {
    int n4 = (int)(n / 4);
    f2h_kernel<<<(n4 + 255) / 256, 256>>>((const float4*)s, (uint2*)d, n4);
}

extern "C" void kernel_launch(void* const* d_in, const int* in_sizes, int n_in,
                              void* d_out, int out_size) {
    const float* hidden    = (const float*)d_in[0];
    const float* w_q_down  = (const float*)d_in[3];
    const float* q_norm_w  = (const float*)d_in[4];
    const float* w_q_up    = (const float*)d_in[5];
    const float* w_kv_down = (const float*)d_in[6];
    const float* kv_norm_w = (const float*)d_in[7];
    const float* w_kv_up   = (const float*)d_in[8];
    const float* w_out     = (const float*)d_in[9];
    float* outp = (float*)d_out;

    void* p;
    __half *hid16, *wqd, *wqup, *wkvd, *wkvup, *wout;
    __half *qtmp, *qbig, *c, *kv, *Q, *Kk, *Vt, *ctx, *attn16;
    float* attn_fb;
    cudaGetSymbolAddress(&p, g_hidden16); hid16 = (__half*)p;
    cudaGetSymbolAddress(&p, g_wqd16);    wqd   = (__half*)p;
    cudaGetSymbolAddress(&p, g_wqup16);   wqup  = (__half*)p;
    cudaGetSymbolAddress(&p, g_wkvd16);   wkvd  = (__half*)p;
    cudaGetSymbolAddress(&p, g_wkvup16);  wkvup = (__half*)p;
    cudaGetSymbolAddress(&p, g_wout16);   wout  = (__half*)p;
    cudaGetSymbolAddress(&p, g_qtmp16);   qtmp  = (__half*)p;
    cudaGetSymbolAddress(&p, g_qbig16);   qbig  = (__half*)p;
    cudaGetSymbolAddress(&p, g_c16);      c     = (__half*)p;
    cudaGetSymbolAddress(&p, g_kv16);     kv    = (__half*)p;
    cudaGetSymbolAddress(&p, g_Q16);      Q     = (__half*)p;
    cudaGetSymbolAddress(&p, g_K16);      Kk    = (__half*)p;
    cudaGetSymbolAddress(&p, g_Vt16);     Vt    = (__half*)p;
    cudaGetSymbolAddress(&p, g_ctx16);    ctx   = (__half*)p;
    cudaGetSymbolAddress(&p, g_attn16);   attn16= (__half*)p;
    cudaGetSymbolAddress(&p, g_attn_fb);  attn_fb = (float*)p;

    const long long OUT_ELEMS  = (long long)ROWS * HID;
    const long long ATTN_ELEMS = (long long)BATCH * NH * SEQ * SEQ;
    float* attn = ((long long)out_size >= OUT_ELEMS + ATTN_ELEMS) ? (outp + OUT_ELEMS)
                                                                  : attn_fb;

    static int inited = 0;
    if (!inited) {
        cudaFuncSetAttribute(gemm_h16, cudaFuncAttributeMaxDynamicSharedMemorySize, GSMEM_BYTES);
        inited = 1;
    }
    dim3 thr(256);

    // fp32 -> fp16 conversions (inputs + weights)
    conv(hidden,    hid16, (long long)ROWS * HID);
    conv(w_q_down,  wqd,   (long long)1536 * HID);
    conv(w_q_up,    wqup,  (long long)3072 * 1536);
    conv(w_kv_down, wkvd,  (long long)576 * HID);
    conv(w_kv_up,   wkvup, (long long)4096 * 512);
    conv(w_out,     wout,  (long long)HID * HID);

    // q = hidden @ w_q_down^T   [4096,1536] K=2048
    gemm_h16<<<dim3(1536/128, ROWS/128, 1), thr, GSMEM_BYTES>>>(
        hid16, wqd, qtmp, ROWS, 1536, HID, HID, HID, 1536,
        1, 0, 0, 0, 0, 0, 0, 1.0f, 0, 1);
    rmsnorm16<<<ROWS, 256>>>(qtmp, q_norm_w, 1536, 1536);

    // q = qn @ w_q_up^T   [4096,3072] K=1536
    gemm_h16<<<dim3(3072/128, ROWS/128, 1), thr, GSMEM_BYTES>>>(
        qtmp, wqup, qbig, ROWS, 3072, 1536, 1536, 1536, 3072,
        1, 0, 0, 0, 0, 0, 0, 1.0f, 0, 1);

    // c = hidden @ w_kv_down^T   [4096,576] K=2048
    gemm_h16<<<dim3((576 + 127)/128, ROWS/128, 1), thr, GSMEM_BYTES>>>(
        hid16, wkvd, c, ROWS, 576, HID, HID, HID, 576,
        1, 0, 0, 0, 0, 0, 0, 1.0f, 0, 1);
    rmsnorm16<<<ROWS, 256>>>(c, kv_norm_w, 512, 576);

    // kv = ckv_n @ w_kv_up^T   [4096,4096] K=512 (lda=576)
    gemm_h16<<<dim3(4096/128, ROWS/128, 1), thr, GSMEM_BYTES>>>(
        c, wkvup, kv, ROWS, 4096, 512, 576, 512, 4096,
        1, 0, 0, 0, 0, 0, 0, 1.0f, 0, 1);

    // RoPE + pack (V transposed)
    rope_pack16<<<ROWS, 256>>>(qbig, c, kv, Q, Kk, Vt);

    // scores = Q K^T / sqrt(192), causal tile-skip, batched over 32 (b,h), fp32 out
    float alpha = rsqrtf((float)DQK);
    gemm_h16<<<dim3(SEQ/128, SEQ/128, BATCH*NH), thr, GSMEM_BYTES>>>(
        Q, Kk, attn, SEQ, SEQ, DQK, DQK, DQK, SEQ,
        1, (long long)SEQ*DQK, 0,
        (long long)SEQ*DQK, 0,
        (long long)SEQ*SEQ, 0,
        alpha, 1, 0);

    // softmax -> fp32 attn (output) + fp16 copy
    softmax_causal<<<BATCH*NH*SEQ, 128>>>(attn, attn16);

    // ctx = attn16 @ Vt^T : NT, causal K-truncation, fp16 out
    gemm_h16<<<dim3(1, SEQ/128, BATCH*NH), thr, GSMEM_BYTES>>>(
        attn16, Vt, ctx, SEQ, DV, SEQ, SEQ, SEQ, NH*DV,
        NH,
        (long long)NH*SEQ*SEQ, (long long)SEQ*SEQ,
        (long long)NH*DV*SEQ,  (long long)DV*SEQ,
        (long long)SEQ*NH*DV,  (long long)DV,
        1.0f, 2, 1);

    // out = ctx @ w_out^T   [4096,2048] K=2048, fp32 out
    gemm_h16<<<dim3(HID/128, ROWS/128, 1), thr, GSMEM_BYTES>>>(
        ctx, wout, outp, ROWS, HID, NH*DV, NH*DV, NH*DV, HID,
        1, 0, 0, 0, 0, 0, 0, 1.0f, 0, 0);
}

// round 7
// speedup vs baseline: 4.9281x; 1.0689x over previous
#include <cuda_runtime.h>
#include <cuda_fp16.h>
#include <math.h>
#include <stdint.h>

#define BATCH 2
#define SEQ   2048
#define HID   2048
#define NH    16
#define DNOPE 128
#define DROPE 64
#define DV    128
#define DQK   192
#define LORA  512
#define ROWS  (BATCH*SEQ)   // 4096
#define NS    5             // cp.async pipeline stages (single-sync design)

// ---------------- scratch (static device memory; no allocations) ----------------
__device__ __half g_hidden16[(size_t)ROWS*HID];
__device__ __half g_wqd16 [(size_t)1536*HID];
__device__ __half g_wqup16[(size_t)3072*1536];
__device__ __half g_wkvd16[(size_t)576*HID];
__device__ __half g_wkvup16[(size_t)4096*512];
__device__ __half g_wout16[(size_t)HID*HID];
__device__ __half g_qtmp16[(size_t)ROWS*1536];
__device__ __half g_qbig16[(size_t)ROWS*3072];
__device__ __half g_c16   [(size_t)ROWS*576];
__device__ __half g_kv16  [(size_t)ROWS*4096];
__device__ __half g_Q16   [(size_t)BATCH*NH*SEQ*DQK];
__device__ __half g_K16   [(size_t)BATCH*NH*SEQ*DQK];
__device__ __half g_Vt16  [(size_t)BATCH*NH*DV*SEQ];   // V transposed per (b,h)
__device__ __half g_ctx16 [(size_t)ROWS*NH*DV];
__device__ __half g_attn16[(size_t)BATCH*NH*SEQ*SEQ];  // fp16 attn for attn@V
__device__ float  g_attn_fb[(size_t)BATCH*NH*SEQ*SEQ]; // fallback fp32 attn

__device__ __forceinline__ uint32_t smem_u32(const void* p) {
    uint32_t a;
    asm("{ .reg .u64 t; cvta.to.shared.u64 t, %1; cvt.u32.u64 %0, t; }" : "=r"(a) : "l"(p));
    return a;
}

#define MMA_F16(ac, ar, br)                                                       \
    asm volatile("mma.sync.aligned.m16n8k16.row.col.f32.f16.f16.f32 "             \
                 "{%0,%1,%2,%3}, {%4,%5,%6,%7}, {%8,%9}, {%0,%1,%2,%3};"          \
                 : "+f"((ac)[0]), "+f"((ac)[1]), "+f"((ac)[2]), "+f"((ac)[3])     \
                 : "r"((ar)[0]), "r"((ar)[1]), "r"((ar)[2]), "r"((ar)[3]),        \
                   "r"((br)[0]), "r"((br)[1]))

// ---------------- fp32 -> fp16 conversion ----------------
__global__ __launch_bounds__(256) void f2h_kernel(
    const float4* __restrict__ src, uint2* __restrict__ dst, int n4)
{
    int i = blockIdx.x * blockDim.x + threadIdx.x;
    if (i < n4) {
        float4 v = src[i];
        __half2 a = __floats2half2_rn(v.x, v.y);
        __half2 b = __floats2half2_rn(v.z, v.w);
        dst[i] = make_uint2(*(uint32_t*)&a, *(uint32_t*)&b);
    }
}

// ---------------- fp16 mma.sync NT GEMM, cp.async 5-stage single-sync pipeline ---
// C[m,n] = alpha * sum_k A[m,k]*B[n,k] ; A,B fp16 in gmem, fp32 accumulate.
// CTA 128x128, BK=32, 8 warps, warp tile 64x32 (4x4 of m16n8k16), 2 CTAs/SM.
// SMEM/stage: A 8KB + B 8KB; rows of 16 words, 8B granules XOR-swizzled by
// (row&7)*2 words -> conflict-free LDS.32 fragment loads (verified R4-R6).
// Single __syncthreads per chunk: with 5 stages, the stage filled at iter kt
// ((kt+4)%5) was last READ in mma(kt-1), complete before this iter's barrier.
// mode: 0 dense, 1 causal tile-skip, 2 causal K-truncation (heavy-first order).
#define GSMEM_BYTES (NS * 16384)

__global__ __launch_bounds__(256, 2) void gemm_h16(
    const __half* __restrict__ A, const __half* __restrict__ B, void* __restrict__ Cv,
    int M, int N, int K, int lda, int ldb, int ldc,
    int zdiv, long long sA1, long long sA2,
    long long sB1, long long sB2, long long sC1, long long sC2,
    float alpha, int mode, int outhalf)
{
    int z  = blockIdx.z;
    int my = (mode == 2) ? (gridDim.y - 1 - blockIdx.y) : blockIdx.y;  // heavy-first
    int m0 = my * 128;
    int n0 = blockIdx.x * 128;
    if (mode == 1 && n0 > m0) return;

    const __half* Ab = A + (long long)(z / zdiv) * sA1 + (long long)(z % zdiv) * sA2;
    const __half* Bb = B + (long long)(z / zdiv) * sB1 + (long long)(z % zdiv) * sB2;
    long long coff = (long long)(z / zdiv) * sC1 + (long long)(z % zdiv) * sC2;

    extern __shared__ uint32_t sm[];
    uint32_t smb = smem_u32(sm);

    int t    = threadIdx.x;
    int lane = t & 31;
    int wid  = t >> 5;
    int g    = lane >> 2;
    int t4   = lane & 3;
    int wm   = wid >> 2;        // 0..1
    int wn   = wid & 3;         // 0..3

    int kEnd = K;
    if (mode == 2) { int ke = m0 + 128; kEnd = (ke < K) ? ke : K; }
    int nk = kEnd >> 5;

    float acc[4][4][4];
    #pragma unroll
    for (int mi = 0; mi < 4; mi++)
        #pragma unroll
        for (int ni = 0; ni < 4; ni++)
            #pragma unroll
            for (int r = 0; r < 4; r++) acc[mi][ni][r] = 0.0f;

    int srow = t >> 3;          // staging: row = srow + i*32 ; 8B chunk = t&7
    int sch  = t & 7;

    auto issue = [&](int kt, int st) {
        int k0 = kt << 5;
        uint32_t sA = smb + st * 16384;
        uint32_t sB = sA + 8192;
        #pragma unroll
        for (int i = 0; i < 4; i++) {
            int row = srow + i * 32;
            uint32_t woff = (uint32_t)(row * 16 + ((sch * 2) ^ ((row & 7) * 2))) * 4;
            const __half* ga = Ab + (size_t)(m0 + row) * lda + k0 + sch * 4;
            asm volatile("cp.async.ca.shared.global [%0], [%1], 8;"
                         :: "r"(sA + woff), "l"(ga));
            int brow = n0 + row;
            const __half* gb = Bb + (size_t)(brow < N ? brow : 0) * ldb + k0 + sch * 4;
            int ssz = (brow < N) ? 8 : 0;
            asm volatile("cp.async.ca.shared.global [%0], [%1], 8, %2;"
                         :: "r"(sB + woff), "l"(gb), "r"(ssz));
        }
    };

    auto mma_chunk = [&](int st) {
        const uint32_t* A_ = sm + st * 4096;
        const uint32_t* B_ = A_ + 2048;
        int sxg = 2 * g;
        #pragma unroll
        for (int ks = 0; ks < 2; ks++) {
            int kw0 = (ks * 8 + t4) ^ sxg;
            int kw1 = (ks * 8 + t4 + 4) ^ sxg;
            uint32_t af[4][4], bf[4][2];
            #pragma unroll
            for (int mi = 0; mi < 4; mi++) {
                int r0 = wm * 64 + mi * 16 + g;
                af[mi][0] = A_[r0 * 16 + kw0];
                af[mi][1] = A_[(r0 + 8) * 16 + kw0];
                af[mi][2] = A_[r0 * 16 + kw1];
                af[mi][3] = A_[(r0 + 8) * 16 + kw1];
            }
            #pragma unroll
            for (int ni = 0; ni < 4; ni++) {
                int n = wn * 32 + ni * 8 + g;
                bf[ni][0] = B_[n * 16 + kw0];
                bf[ni][1] = B_[n * 16 + kw1];
            }
            #pragma unroll
            for (int mi = 0; mi < 4; mi++)
                #pragma unroll
                for (int ni = 0; ni < 4; ni++)
                    MMA_F16(acc[mi][ni], af[mi], bf[ni]);
        }
    };

    // prologue: 4 stages in flight
    #pragma unroll
    for (int s = 0; s < NS - 1; s++) {
        if (s < nk) issue(s, s);
        asm volatile("cp.async.commit_group;" ::: "memory");
    }

    int st = 0, stw = NS - 1;   // read stage, write stage (rotating mod NS)
    for (int kt = 0; kt < nk; kt++) {
        asm volatile("cp.async.wait_group %0;" :: "n"(NS - 2) : "memory");
        __syncthreads();
        mma_chunk(st);
        int nxt = kt + NS - 1;
        if (nxt < nk) issue(nxt, stw);
        asm volatile("cp.async.commit_group;" ::: "memory");
        if (++st == NS) st = 0;
        if (++stw == NS) stw = 0;
    }

    // epilogue
    #pragma unroll
    for (int mi = 0; mi < 4; mi++) {
        int row = m0 + wm * 64 + mi * 16 + g;
        #pragma unroll
        for (int ni = 0; ni < 4; ni++) {
            int col = n0 + wn * 32 + ni * 8 + 2 * t4;
            if (col < N) {
                if (outhalf) {
                    __half* Cb = (__half*)Cv + coff;
                    __half2 h0 = __floats2half2_rn(alpha * acc[mi][ni][0], alpha * acc[mi][ni][1]);
                    __half2 h1 = __floats2half2_rn(alpha * acc[mi][ni][2], alpha * acc[mi][ni][3]);
                    *(__half2*)(Cb + (size_t)row * ldc + col)       = h0;
                    *(__half2*)(Cb + (size_t)(row + 8) * ldc + col) = h1;
                } else {
                    float* Cb = (float*)Cv + coff;
                    float2 v0 = make_float2(alpha * acc[mi][ni][0], alpha * acc[mi][ni][1]);
                    float2 v1 = make_float2(alpha * acc[mi][ni][2], alpha * acc[mi][ni][3]);
                    *(float2*)(Cb + (size_t)row * ldc + col)       = v0;
                    *(float2*)(Cb + (size_t)(row + 8) * ldc + col) = v1;
                }
            }
        }
    }
}

// ---------------- block reductions ----------------
__device__ __forceinline__ float blockReduceSum(float v) {
    __shared__ float sh[32];
    int lane = threadIdx.x & 31, w = threadIdx.x >> 5;
    #pragma unroll
    for (int o = 16; o > 0; o >>= 1) v += __shfl_xor_sync(0xffffffffu, v, o);
    __syncthreads();
    if (lane == 0) sh[w] = v;
    __syncthreads();
    int nw = (blockDim.x + 31) >> 5;
    float r = (threadIdx.x < nw) ? sh[threadIdx.x] : 0.0f;
    if (w == 0) {
        #pragma unroll
        for (int o = 16; o > 0; o >>= 1) r += __shfl_xor_sync(0xffffffffu, r, o);
        if (lane == 0) sh[0] = r;
    }
    __syncthreads();
    return sh[0];
}
__device__ __forceinline__ float blockReduceMax(float v) {
    __shared__ float sh[32];
    int lane = threadIdx.x & 31, w = threadIdx.x >> 5;
    #pragma unroll
    for (int o = 16; o > 0; o >>= 1) v = fmaxf(v, __shfl_xor_sync(0xffffffffu, v, o));
    __syncthreads();
    if (lane == 0) sh[w] = v;
    __syncthreads();
    int nw = (blockDim.x + 31) >> 5;
    float r = (threadIdx.x < nw) ? sh[threadIdx.x] : -INFINITY;
    if (w == 0) {
        #pragma unroll
        for (int o = 16; o > 0; o >>= 1) r = fmaxf(r, __shfl_xor_sync(0xffffffffu, r, o));
        if (lane == 0) sh[0] = r;
    }
    __syncthreads();
    return sh[0];
}

// ---------------- RMSNorm fp16 (in place) ----------------
__global__ __launch_bounds__(256) void rmsnorm16(
    __half* __restrict__ x, const float* __restrict__ w, int W, int stride)
{
    __half* row = x + (long long)blockIdx.x * stride;
    float ss = 0.0f;
    for (int i = threadIdx.x; i < W; i += blockDim.x) {
        float v = __half2float(row[i]); ss += v * v;
    }
    ss = blockReduceSum(ss);
    float sc = rsqrtf(ss / (float)W + 1e-6f);
    for (int i = threadIdx.x; i < W; i += blockDim.x)
        row[i] = __float2half(__half2float(row[i]) * sc * w[i]);
}

// ---------------- RoPE + pack fp16 (V written transposed) ----------------
__global__ __launch_bounds__(256) void rope_pack16(
    const __half* __restrict__ q,   // [ROWS,3072]
    const __half* __restrict__ c,   // [ROWS,576]
    const __half* __restrict__ kv,  // [ROWS,4096]
    __half* __restrict__ Qo,        // [B,NH,S,192]
    __half* __restrict__ Ko,        // [B,NH,S,192]
    __half* __restrict__ Vt)        // [B,NH,DV,S]
{
    int row = blockIdx.x;
    int b = row / SEQ, s = row % SEQ;
    int t = threadIdx.x;

    __shared__ float cs[32], sn[32];
    __shared__ __half kr[64];
    if (t < 32) {
        float f = exp10f(-(float)t / 8.0f);   // 10000^(-t/32)
        float ang = (float)s * f;
        sincosf(ang, &sn[t], &cs[t]);
    }
    __syncthreads();
    if (t < 64) {
        const __half* kx = c + (long long)row * 576 + 512;
        int j = t; float v;
        if (j < 32) v = __half2float(kx[2*j]) * cs[j] - __half2float(kx[2*j+1]) * sn[j];
        else { int i = j - 32; v = __half2float(kx[2*i+1]) * cs[i] + __half2float(kx[2*i]) * sn[i]; }
        kr[j] = __float2half(v);
    }
    __syncthreads();

    const __half* qrow = q + (long long)row * 3072;
    for (int idx = t; idx < NH * DQK; idx += 256) {
        int h = idx / DQK, d = idx % DQK;
        __half v;
        if (d < DNOPE) v = qrow[h * DQK + d];
        else {
            int j = d - DNOPE;
            const __half* qx = qrow + h * DQK + DNOPE;
            float vv;
            if (j < 32) vv = __half2float(qx[2*j]) * cs[j] - __half2float(qx[2*j+1]) * sn[j];
            else { int i = j - 32; vv = __half2float(qx[2*i+1]) * cs[i] + __half2float(qx[2*i]) * sn[i]; }
            v = __float2half(vv);
        }
        Qo[((long long)(b * NH + h) * SEQ + s) * DQK + d] = v;
    }

    const __half* kvrow = kv + (long long)row * 4096;
    for (int idx = t; idx < NH * DQK; idx += 256) {
        int h = idx / DQK, d = idx % DQK;
        __half v = (d < DNOPE) ? kvrow[h * 256 + d] : kr[d - DNOPE];
        Ko[((long long)(b * NH + h) * SEQ + s) * DQK + d] = v;
    }
    for (int idx = t; idx < NH * DV; idx += 256) {
        int h = idx / DV, d = idx % DV;
        Vt[((long long)(b * NH + h) * DV + d) * SEQ + s] = kvrow[h * 256 + DNOPE + d];
    }
}

// ---------------- causal softmax: fp32 out + trimmed fp16 copy ----------------
__global__ __launch_bounds__(128) void softmax_causal(
    float* __restrict__ attn, __half* __restrict__ attn16)
{
    long long r = blockIdx.x;
    int q = (int)(r % SEQ);
    float*  row   = attn   + r * SEQ;
    __half* row16 = attn16 + r * SEQ;
    int t = threadIdx.x;
    int len = q + 1;
    int len16 = (len + 127) & ~127;   // attn@V never reads past the diagonal tile

    float vals[16];
    float mx = -INFINITY;
    #pragma unroll
    for (int it = 0; it < 16; it++) {
        int i = t + it * 128;
        float v = (i < len) ? row[i] : -INFINITY;
        vals[it] = v; mx = fmaxf(mx, v);
    }
    mx = blockReduceMax(mx);

    float sum = 0.0f;
    #pragma unroll
    for (int it = 0; it < 16; it++) {
        int i = t + it * 128;
        float e = (i < len) ? __expf(vals[it] - mx) : 0.0f;
        vals[it] = e; sum += e;
    }
    sum = blockReduceSum(sum);
    float inv = 1.0f / sum;

    #pragma unroll
    for (int it = 0; it < 16; it++) {
        int i = t + it * 128;
        float o = (i < len) ? vals[it] * inv : 0.0f;
        row[i] = o;
        if (i < len16) row16[i] = __float2half(o);
    }
}

// ---------------- host launch ----------------
static inline void conv(const float* s, __half* d, long long n) {
    int n4 = (int)(n / 4);
    f2h_kernel<<<(n4 + 255) / 256, 256>>>((const float4*)s, (uint2*)d, n4);
}

extern "C" void kernel_launch(void* const* d_in, const int* in_sizes, int n_in,
                              void* d_out, int out_size) {
    const float* hidden    = (const float*)d_in[0];
    const float* w_q_down  = (const float*)d_in[3];
    const float* q_norm_w  = (const float*)d_in[4];
    const float* w_q_up    = (const float*)d_in[5];
    const float* w_kv_down = (const float*)d_in[6];
    const float* kv_norm_w = (const float*)d_in[7];
    const float* w_kv_up   = (const float*)d_in[8];
    const float* w_out     = (const float*)d_in[9];
    float* outp = (float*)d_out;

    void* p;
    __half *hid16, *wqd, *wqup, *wkvd, *wkvup, *wout;
    __half *qtmp, *qbig, *c, *kv, *Q, *Kk, *Vt, *ctx, *attn16;
    float* attn_fb;
    cudaGetSymbolAddress(&p, g_hidden16); hid16 = (__half*)p;
    cudaGetSymbolAddress(&p, g_wqd16);    wqd   = (__half*)p;
    cudaGetSymbolAddress(&p, g_wqup16);   wqup  = (__half*)p;
    cudaGetSymbolAddress(&p, g_wkvd16);   wkvd  = (__half*)p;
    cudaGetSymbolAddress(&p, g_wkvup16);  wkvup = (__half*)p;
    cudaGetSymbolAddress(&p, g_wout16);   wout  = (__half*)p;
    cudaGetSymbolAddress(&p, g_qtmp16);   qtmp  = (__half*)p;
    cudaGetSymbolAddress(&p, g_qbig16);   qbig  = (__half*)p;
    cudaGetSymbolAddress(&p, g_c16);      c     = (__half*)p;
    cudaGetSymbolAddress(&p, g_kv16);     kv    = (__half*)p;
    cudaGetSymbolAddress(&p, g_Q16);      Q     = (__half*)p;
    cudaGetSymbolAddress(&p, g_K16);      Kk    = (__half*)p;
    cudaGetSymbolAddress(&p, g_Vt16);     Vt    = (__half*)p;
    cudaGetSymbolAddress(&p, g_ctx16);    ctx   = (__half*)p;
    cudaGetSymbolAddress(&p, g_attn16);   attn16= (__half*)p;
    cudaGetSymbolAddress(&p, g_attn_fb);  attn_fb = (float*)p;

    const long long OUT_ELEMS  = (long long)ROWS * HID;
    const long long ATTN_ELEMS = (long long)BATCH * NH * SEQ * SEQ;
    float* attn = ((long long)out_size >= OUT_ELEMS + ATTN_ELEMS) ? (outp + OUT_ELEMS)
                                                                  : attn_fb;

    static int inited = 0;
    if (!inited) {
        cudaFuncSetAttribute(gemm_h16, cudaFuncAttributeMaxDynamicSharedMemorySize, GSMEM_BYTES);
        inited = 1;
    }
    dim3 thr(256);

    // fp32 -> fp16 conversions (inputs + weights)
    conv(hidden,    hid16, (long long)ROWS * HID);
    conv(w_q_down,  wqd,   (long long)1536 * HID);
    conv(w_q_up,    wqup,  (long long)3072 * 1536);
    conv(w_kv_down, wkvd,  (long long)576 * HID);
    conv(w_kv_up,   wkvup, (long long)4096 * 512);
    conv(w_out,     wout,  (long long)HID * HID);

    // q = hidden @ w_q_down^T   [4096,1536] K=2048
    gemm_h16<<<dim3(1536/128, ROWS/128, 1), thr, GSMEM_BYTES>>>(
        hid16, wqd, qtmp, ROWS, 1536, HID, HID, HID, 1536,
        1, 0, 0, 0, 0, 0, 0, 1.0f, 0, 1);
    rmsnorm16<<<ROWS, 256>>>(qtmp, q_norm_w, 1536, 1536);

    // q = qn @ w_q_up^T   [4096,3072] K=1536
    gemm_h16<<<dim3(3072/128, ROWS/128, 1), thr, GSMEM_BYTES>>>(
        qtmp, wqup, qbig, ROWS, 3072, 1536, 1536, 1536, 3072,
        1, 0, 0, 0, 0, 0, 0, 1.0f, 0, 1);

    // c = hidden @ w_kv_down^T   [4096,576] K=2048
    gemm_h16<<<dim3((576 + 127)/128, ROWS/128, 1), thr, GSMEM_BYTES>>>(
        hid16, wkvd, c, ROWS, 576, HID, HID, HID, 576,
        1, 0, 0, 0, 0, 0, 0, 1.0f, 0, 1);
    rmsnorm16<<<ROWS, 256>>>(c, kv_norm_w, 512, 576);

    // kv = ckv_n @ w_kv_up^T   [4096,4096] K=512 (lda=576)
    gemm_h16<<<dim3(4096/128, ROWS/128, 1), thr, GSMEM_BYTES>>>(
        c, wkvup, kv, ROWS, 4096, 512, 576, 512, 4096,
        1, 0, 0, 0, 0, 0, 0, 1.0f, 0, 1);

    // RoPE + pack (V transposed)
    rope_pack16<<<ROWS, 256>>>(qbig, c, kv, Q, Kk, Vt);

    // scores = Q K^T / sqrt(192), causal tile-skip, batched over 32 (b,h), fp32 out
    float alpha = rsqrtf((float)DQK);
    gemm_h16<<<dim3(SEQ/128, SEQ/128, BATCH*NH), thr, GSMEM_BYTES>>>(
        Q, Kk, attn, SEQ, SEQ, DQK, DQK, DQK, SEQ,
        1, (long long)SEQ*DQK, 0,
        (long long)SEQ*DQK, 0,
        (long long)SEQ*SEQ, 0,
        alpha, 1, 0);

    // softmax -> fp32 attn (output) + trimmed fp16 copy
    softmax_causal<<<BATCH*NH*SEQ, 128>>>(attn, attn16);

    // ctx = attn16 @ Vt^T : NT, causal K-truncation, heavy-first, fp16 out
    gemm_h16<<<dim3(1, SEQ/128, BATCH*NH), thr, GSMEM_BYTES>>>(
        attn16, Vt, ctx, SEQ, DV, SEQ, SEQ, SEQ, NH*DV,
        NH,
        (long long)NH*SEQ*SEQ, (long long)SEQ*SEQ,
        (long long)NH*DV*SEQ,  (long long)DV*SEQ,
        (long long)SEQ*NH*DV,  (long long)DV,
        1.0f, 2, 1);

    // out = ctx @ w_out^T   [4096,2048] K=2048, fp32 out
    gemm_h16<<<dim3(HID/128, ROWS/128, 1), thr, GSMEM_BYTES>>>(
        ctx, wout, outp, ROWS, HID, NH*DV, NH*DV, NH*DV, HID,
        1, 0, 0, 0, 0, 0, 0, 1.0f, 0, 0);
}

// round 8
// speedup vs baseline: 6.2869x; 1.2757x over previous
#include <cuda_runtime.h>
#include <cuda_fp16.h>
#include <math.h>
#include <stdint.h>

#define BATCH 2
#define SEQ   2048
#define HID   2048
#define NH    16
#define DNOPE 128
#define DROPE 64
#define DV    128
#define DQK   192
#define LORA  512
#define ROWS  (BATCH*SEQ)   // 4096
#define NS    5             // cp.async pipeline stages (single-sync design)

// ---------------- scratch (static device memory; no allocations) ----------------
__device__ __half g_hidden16[(size_t)ROWS*HID];
__device__ __half g_wqd16 [(size_t)1536*HID];
__device__ __half g_wqup16[(size_t)3072*1536];
__device__ __half g_wkvd16[(size_t)576*HID];
__device__ __half g_wkvup16[(size_t)4096*512];
__device__ __half g_wout16[(size_t)HID*HID];
__device__ __half g_qtmp16[(size_t)ROWS*1536];
__device__ __half g_qbig16[(size_t)ROWS*3072];
__device__ __half g_c16   [(size_t)ROWS*576];
__device__ __half g_kv16  [(size_t)ROWS*4096];
__device__ __half g_Q16   [(size_t)BATCH*NH*SEQ*DQK];
__device__ __half g_K16   [(size_t)BATCH*NH*SEQ*DQK];
__device__ __half g_Vt16  [(size_t)BATCH*NH*DV*SEQ];   // V transposed per (b,h)
__device__ __half g_ctx16 [(size_t)ROWS*NH*DV];
__device__ __half g_attn16[(size_t)BATCH*NH*SEQ*SEQ];  // fp16 attn for attn@V
__device__ float  g_attn_fb[(size_t)BATCH*NH*SEQ*SEQ]; // fallback fp32 attn

__device__ __forceinline__ uint32_t smem_u32(const void* p) {
    uint32_t a;
    asm("{ .reg .u64 t; cvta.to.shared.u64 t, %1; cvt.u32.u64 %0, t; }" : "=r"(a) : "l"(p));
    return a;
}

#define MMA_F16(ac, ar, br)                                                       \
    asm volatile("mma.sync.aligned.m16n8k16.row.col.f32.f16.f16.f32 "             \
                 "{%0,%1,%2,%3}, {%4,%5,%6,%7}, {%8,%9}, {%0,%1,%2,%3};"          \
                 : "+f"((ac)[0]), "+f"((ac)[1]), "+f"((ac)[2]), "+f"((ac)[3])     \
                 : "r"((ar)[0]), "r"((ar)[1]), "r"((ar)[2]), "r"((ar)[3]),        \
                   "r"((br)[0]), "r"((br)[1]))

#define LDSM_X4(r0, r1, r2, r3, addr)                                             \
    asm volatile("ldmatrix.sync.aligned.m8n8.x4.shared.b16 {%0,%1,%2,%3}, [%4];"  \
                 : "=r"(r0), "=r"(r1), "=r"(r2), "=r"(r3) : "r"(addr))

// ---------------- fp32 -> fp16 conversion ----------------
__global__ __launch_bounds__(256) void f2h_kernel(
    const float4* __restrict__ src, uint2* __restrict__ dst, int n4)
{
    int i = blockIdx.x * blockDim.x + threadIdx.x;
    if (i < n4) {
        float4 v = src[i];
        __half2 a = __floats2half2_rn(v.x, v.y);
        __half2 b = __floats2half2_rn(v.z, v.w);
        dst[i] = make_uint2(*(uint32_t*)&a, *(uint32_t*)&b);
    }
}

// ---------------- fp16 mma.sync NT GEMM: cp.async.cg(16B) + ldmatrix.x4 ---------
// C[m,n] = alpha * sum_k A[m,k]*B[n,k] ; fp16 gmem, fp32 accumulate.
// CTA 128x128, BK=32, 8 warps (warp 64x32), 2 CTAs/SM, 5-stage single-sync pipe.
// SMEM layout: row = 32 halves (64B) = 4 x 16B units; unit swizzle
// u' = u ^ ((row>>1)&3) -> each 8-row ldmatrix phase hits 8 distinct 16B slots
// (all 32 banks), conflict-free; 16B cp.async granules land contiguously.
// mode: 0 dense, 1 causal tile-skip, 2 causal K-truncation (heavy-first order).
#define GSMEM_BYTES (NS * 16384)

__global__ __launch_bounds__(256, 2) void gemm_h16(
    const __half* __restrict__ A, const __half* __restrict__ B, void* __restrict__ Cv,
    int M, int N, int K, int lda, int ldb, int ldc,
    int zdiv, long long sA1, long long sA2,
    long long sB1, long long sB2, long long sC1, long long sC2,
    float alpha, int mode, int outhalf)
{
    int z  = blockIdx.z;
    int my = (mode == 2) ? (gridDim.y - 1 - blockIdx.y) : blockIdx.y;  // heavy-first
    int m0 = my * 128;
    int n0 = blockIdx.x * 128;
    if (mode == 1 && n0 > m0) return;

    const __half* Ab = A + (long long)(z / zdiv) * sA1 + (long long)(z % zdiv) * sA2;
    const __half* Bb = B + (long long)(z / zdiv) * sB1 + (long long)(z % zdiv) * sB2;
    long long coff = (long long)(z / zdiv) * sC1 + (long long)(z % zdiv) * sC2;

    extern __shared__ uint32_t sm[];
    uint32_t smb = smem_u32(sm);

    int t    = threadIdx.x;
    int lane = t & 31;
    int wid  = t >> 5;
    int g    = lane >> 2;
    int t4   = lane & 3;
    int wm   = wid >> 2;        // 0..1
    int wn   = wid & 3;         // 0..3

    int kEnd = K;
    if (mode == 2) { int ke = m0 + 128; kEnd = (ke < K) ? ke : K; }
    int nk = kEnd >> 5;

    float acc[4][4][4];
    #pragma unroll
    for (int mi = 0; mi < 4; mi++)
        #pragma unroll
        for (int ni = 0; ni < 4; ni++)
            #pragma unroll
            for (int r = 0; r < 4; r++) acc[mi][ni][r] = 0.0f;

    // ---- staging geometry: thread t covers 16B unit (row = t>>2 + 64*i, u = t&3)
    int urow = t >> 2;            // 0..63
    int uu   = t & 3;
    int sxu  = uu ^ ((urow >> 1) & 3);   // swizzled unit (invariant under row+=64)

    auto issue = [&](int kt, int st) {
        int k0 = kt << 5;
        uint32_t sA = smb + st * 16384;
        uint32_t sB = sA + 8192;
        #pragma unroll
        for (int i = 0; i < 2; i++) {
            int row = urow + i * 64;
            uint32_t dst = (uint32_t)(row * 64 + (sxu << 4));
            const __half* ga = Ab + (size_t)(m0 + row) * lda + k0 + uu * 8;
            asm volatile("cp.async.cg.shared.global [%0], [%1], 16;"
                         :: "r"(sA + dst), "l"(ga));
            int brow = n0 + row;
            const __half* gb = Bb + (size_t)(brow < N ? brow : 0) * ldb + k0 + uu * 8;
            int ssz = (brow < N) ? 16 : 0;
            asm volatile("cp.async.cg.shared.global [%0], [%1], 16, %2;"
                         :: "r"(sB + dst), "l"(gb), "r"(ssz));
        }
    };

    // ---- ldmatrix per-lane address components
    int m_idx = lane >> 3;        // matrix index 0..3
    int rin   = lane & 7;
    // A: matrices [m0-7,klo],[m8-15,klo],[m0-7,khi],[m8-15,khi]
    int arow0 = wm * 64 + rin + (m_idx & 1) * 8;
    int aun   = m_idx >> 1;                   // 0=klo,1=khi
    int axs   = (arow0 >> 1) & 3;
    uint32_t aoffb = (uint32_t)(arow0 * 64);
    // B: matrices [n0-7,klo],[n0-7,khi],[n8-15,klo],[n8-15,khi]
    int brow0 = wn * 32 + rin + (m_idx >> 1) * 8;
    int bun   = m_idx & 1;
    int bxs   = (brow0 >> 1) & 3;
    uint32_t boffb = (uint32_t)(brow0 * 64);

    auto mma_chunk = [&](int st) {
        uint32_t sA = smb + st * 16384;
        uint32_t sB = sA + 8192;
        #pragma unroll
        for (int ks = 0; ks < 2; ks++) {
            uint32_t af[4][4], bf[4][2];
            uint32_t au = (uint32_t)(((2 * ks + aun) ^ axs) << 4);
            uint32_t bu = (uint32_t)(((2 * ks + bun) ^ bxs) << 4);
            #pragma unroll
            for (int mi = 0; mi < 4; mi++)
                LDSM_X4(af[mi][0], af[mi][1], af[mi][2], af[mi][3],
                        sA + aoffb + (uint32_t)(mi * 1024) + au);
            #pragma unroll
            for (int p = 0; p < 2; p++)
                LDSM_X4(bf[2*p][0], bf[2*p][1], bf[2*p+1][0], bf[2*p+1][1],
                        sB + boffb + (uint32_t)(p * 1024) + bu);
            #pragma unroll
            for (int mi = 0; mi < 4; mi++)
                #pragma unroll
                for (int ni = 0; ni < 4; ni++)
                    MMA_F16(acc[mi][ni], af[mi], bf[ni]);
        }
    };

    // prologue: NS-1 stages in flight
    #pragma unroll
    for (int s = 0; s < NS - 1; s++) {
        if (s < nk) issue(s, s);
        asm volatile("cp.async.commit_group;" ::: "memory");
    }

    int st = 0, stw = NS - 1;
    for (int kt = 0; kt < nk; kt++) {
        asm volatile("cp.async.wait_group %0;" :: "n"(NS - 2) : "memory");
        __syncthreads();
        mma_chunk(st);
        int nxt = kt + NS - 1;
        if (nxt < nk) issue(nxt, stw);
        asm volatile("cp.async.commit_group;" ::: "memory");
        if (++st == NS) st = 0;
        if (++stw == NS) stw = 0;
    }

    // epilogue
    #pragma unroll
    for (int mi = 0; mi < 4; mi++) {
        int row = m0 + wm * 64 + mi * 16 + g;
        #pragma unroll
        for (int ni = 0; ni < 4; ni++) {
            int col = n0 + wn * 32 + ni * 8 + 2 * t4;
            if (col < N) {
                if (outhalf) {
                    __half* Cb = (__half*)Cv + coff;
                    __half2 h0 = __floats2half2_rn(alpha * acc[mi][ni][0], alpha * acc[mi][ni][1]);
                    __half2 h1 = __floats2half2_rn(alpha * acc[mi][ni][2], alpha * acc[mi][ni][3]);
                    *(__half2*)(Cb + (size_t)row * ldc + col)       = h0;
                    *(__half2*)(Cb + (size_t)(row + 8) * ldc + col) = h1;
                } else {
                    float* Cb = (float*)Cv + coff;
                    float2 v0 = make_float2(alpha * acc[mi][ni][0], alpha * acc[mi][ni][1]);
                    float2 v1 = make_float2(alpha * acc[mi][ni][2], alpha * acc[mi][ni][3]);
                    *(float2*)(Cb + (size_t)row * ldc + col)       = v0;
                    *(float2*)(Cb + (size_t)(row + 8) * ldc + col) = v1;
                }
            }
        }
    }
}

// ---------------- block reductions (256 threads) ----------------
__device__ __forceinline__ float blockReduceSum(float v) {
    __shared__ float sh[32];
    int lane = threadIdx.x & 31, w = threadIdx.x >> 5;
    #pragma unroll
    for (int o = 16; o > 0; o >>= 1) v += __shfl_xor_sync(0xffffffffu, v, o);
    __syncthreads();
    if (lane == 0) sh[w] = v;
    __syncthreads();
    int nw = (blockDim.x + 31) >> 5;
    float r = (threadIdx.x < nw) ? sh[threadIdx.x] : 0.0f;
    if (w == 0) {
        #pragma unroll
        for (int o = 16; o > 0; o >>= 1) r += __shfl_xor_sync(0xffffffffu, r, o);
        if (lane == 0) sh[0] = r;
    }
    __syncthreads();
    return sh[0];
}
__device__ __forceinline__ float blockReduceMax(float v) {
    __shared__ float sh[32];
    int lane = threadIdx.x & 31, w = threadIdx.x >> 5;
    #pragma unroll
    for (int o = 16; o > 0; o >>= 1) v = fmaxf(v, __shfl_xor_sync(0xffffffffu, v, o));
    __syncthreads();
    if (lane == 0) sh[w] = v;
    __syncthreads();
    int nw = (blockDim.x + 31) >> 5;
    float r = (threadIdx.x < nw) ? sh[threadIdx.x] : -INFINITY;
    if (w == 0) {
        #pragma unroll
        for (int o = 16; o > 0; o >>= 1) r = fmaxf(r, __shfl_xor_sync(0xffffffffu, r, o));
        if (lane == 0) sh[0] = r;
    }
    __syncthreads();
    return sh[0];
}

// ---------------- RMSNorm fp16 (in place) ----------------
__global__ __launch_bounds__(256) void rmsnorm16(
    __half* __restrict__ x, const float* __restrict__ w, int W, int stride)
{
    __half* row = x + (long long)blockIdx.x * stride;
    float ss = 0.0f;
    for (int i = threadIdx.x; i < W; i += blockDim.x) {
        float v = __half2float(row[i]); ss += v * v;
    }
    ss = blockReduceSum(ss);
    float sc = rsqrtf(ss / (float)W + 1e-6f);
    for (int i = threadIdx.x; i < W; i += blockDim.x)
        row[i] = __float2half(__half2float(row[i]) * sc * w[i]);
}

// ---------------- RoPE + pack fp16 (V written transposed) ----------------
__global__ __launch_bounds__(256) void rope_pack16(
    const __half* __restrict__ q,   // [ROWS,3072]
    const __half* __restrict__ c,   // [ROWS,576]
    const __half* __restrict__ kv,  // [ROWS,4096]
    __half* __restrict__ Qo,        // [B,NH,S,192]
    __half* __restrict__ Ko,        // [B,NH,S,192]
    __half* __restrict__ Vt)        // [B,NH,DV,S]
{
    int row = blockIdx.x;
    int b = row / SEQ, s = row % SEQ;
    int t = threadIdx.x;

    __shared__ float cs[32], sn[32];
    __shared__ __half kr[64];
    if (t < 32) {
        float f = exp10f(-(float)t / 8.0f);   // 10000^(-t/32)
        float ang = (float)s * f;
        sincosf(ang, &sn[t], &cs[t]);
    }
    __syncthreads();
    if (t < 64) {
        const __half* kx = c + (long long)row * 576 + 512;
        int j = t; float v;
        if (j < 32) v = __half2float(kx[2*j]) * cs[j] - __half2float(kx[2*j+1]) * sn[j];
        else { int i = j - 32; v = __half2float(kx[2*i+1]) * cs[i] + __half2float(kx[2*i]) * sn[i]; }
        kr[j] = __float2half(v);
    }
    __syncthreads();

    const __half* qrow = q + (long long)row * 3072;
    for (int idx = t; idx < NH * DQK; idx += 256) {
        int h = idx / DQK, d = idx % DQK;
        __half v;
        if (d < DNOPE) v = qrow[h * DQK + d];
        else {
            int j = d - DNOPE;
            const __half* qx = qrow + h * DQK + DNOPE;
            float vv;
            if (j < 32) vv = __half2float(qx[2*j]) * cs[j] - __half2float(qx[2*j+1]) * sn[j];
            else { int i = j - 32; vv = __half2float(qx[2*i+1]) * cs[i] + __half2float(qx[2*i]) * sn[i]; }
            v = __float2half(vv);
        }
        Qo[((long long)(b * NH + h) * SEQ + s) * DQK + d] = v;
    }

    const __half* kvrow = kv + (long long)row * 4096;
    for (int idx = t; idx < NH * DQK; idx += 256) {
        int h = idx / DQK, d = idx % DQK;
        __half v = (d < DNOPE) ? kvrow[h * 256 + d] : kr[d - DNOPE];
        Ko[((long long)(b * NH + h) * SEQ + s) * DQK + d] = v;
    }
    for (int idx = t; idx < NH * DV; idx += 256) {
        int h = idx / DV, d = idx % DV;
        Vt[((long long)(b * NH + h) * DV + d) * SEQ + s] = kvrow[h * 256 + DNOPE + d];
    }
}

// ---------------- causal softmax: vectorized, fp32 out + trimmed fp16 copy -------
__global__ __launch_bounds__(256) void softmax_causal(
    float* __restrict__ attn, __half* __restrict__ attn16)
{
    long long r = blockIdx.x;
    int q = (int)(r % SEQ);
    float4* row4   = (float4*)(attn + r * SEQ);
    uint2*  row16  = (uint2*)(attn16 + r * SEQ);
    int t = threadIdx.x;
    int len = q + 1;
    int len16 = (len + 127) & ~127;   // attn@V never reads past the diagonal tile

    float4 v[2];
    float mx = -INFINITY;
    #pragma unroll
    for (int it = 0; it < 2; it++) {
        int i4 = t + it * 256;
        int base = i4 * 4;
        float4 x = make_float4(-INFINITY, -INFINITY, -INFINITY, -INFINITY);
        if (base < len) {
            x = row4[i4];
            if (base + 1 >= len) x.y = -INFINITY;
            if (base + 2 >= len) x.z = -INFINITY;
            if (base + 3 >= len) x.w = -INFINITY;
        }
        v[it] = x;
        mx = fmaxf(mx, fmaxf(fmaxf(x.x, x.y), fmaxf(x.z, x.w)));
    }
    mx = blockReduceMax(mx);

    float sum = 0.0f;
    #pragma unroll
    for (int it = 0; it < 2; it++) {
        float4 x = v[it];
        x.x = (x.x == -INFINITY) ? 0.0f : __expf(x.x - mx);
        x.y = (x.y == -INFINITY) ? 0.0f : __expf(x.y - mx);
        x.z = (x.z == -INFINITY) ? 0.0f : __expf(x.z - mx);
        x.w = (x.w == -INFINITY) ? 0.0f : __expf(x.w - mx);
        v[it] = x;
        sum += x.x + x.y + x.z + x.w;
    }
    sum = blockReduceSum(sum);
    float inv = 1.0f / sum;

    #pragma unroll
    for (int it = 0; it < 2; it++) {
        int i4 = t + it * 256;
        int base = i4 * 4;
        float4 x = v[it];
        x.x *= inv; x.y *= inv; x.z *= inv; x.w *= inv;
        row4[i4] = x;
        if (base < len16) {
            __half2 a = __floats2half2_rn(x.x, x.y);
            __half2 b = __floats2half2_rn(x.z, x.w);
            row16[i4] = make_uint2(*(uint32_t*)&a, *(uint32_t*)&b);
        }
    }
}

// ---------------- host launch ----------------
static inline void conv(const float* s, __half* d, long long n) {
    int n4 = (int)(n / 4);
    f2h_kernel<<<(n4 + 255) / 256, 256>>>((const float4*)s, (uint2*)d, n4);
}

extern "C" void kernel_launch(void* const* d_in, const int* in_sizes, int n_in,
                              void* d_out, int out_size) {
    const float* hidden    = (const float*)d_in[0];
    const float* w_q_down  = (const float*)d_in[3];
    const float* q_norm_w  = (const float*)d_in[4];
    const float* w_q_up    = (const float*)d_in[5];
    const float* w_kv_down = (const float*)d_in[6];
    const float* kv_norm_w = (const float*)d_in[7];
    const float* w_kv_up   = (const float*)d_in[8];
    const float* w_out     = (const float*)d_in[9];
    float* outp = (float*)d_out;

    void* p;
    __half *hid16, *wqd, *wqup, *wkvd, *wkvup, *wout;
    __half *qtmp, *qbig, *c, *kv, *Q, *Kk, *Vt, *ctx, *attn16;
    float* attn_fb;
    cudaGetSymbolAddress(&p, g_hidden16); hid16 = (__half*)p;
    cudaGetSymbolAddress(&p, g_wqd16);    wqd   = (__half*)p;
    cudaGetSymbolAddress(&p, g_wqup16);   wqup  = (__half*)p;
    cudaGetSymbolAddress(&p, g_wkvd16);   wkvd  = (__half*)p;
    cudaGetSymbolAddress(&p, g_wkvup16);  wkvup = (__half*)p;
    cudaGetSymbolAddress(&p, g_wout16);   wout  = (__half*)p;
    cudaGetSymbolAddress(&p, g_qtmp16);   qtmp  = (__half*)p;
    cudaGetSymbolAddress(&p, g_qbig16);   qbig  = (__half*)p;
    cudaGetSymbolAddress(&p, g_c16);      c     = (__half*)p;
    cudaGetSymbolAddress(&p, g_kv16);     kv    = (__half*)p;
    cudaGetSymbolAddress(&p, g_Q16);      Q     = (__half*)p;
    cudaGetSymbolAddress(&p, g_K16);      Kk    = (__half*)p;
    cudaGetSymbolAddress(&p, g_Vt16);     Vt    = (__half*)p;
    cudaGetSymbolAddress(&p, g_ctx16);    ctx   = (__half*)p;
    cudaGetSymbolAddress(&p, g_attn16);   attn16= (__half*)p;
    cudaGetSymbolAddress(&p, g_attn_fb);  attn_fb = (float*)p;

    const long long OUT_ELEMS  = (long long)ROWS * HID;
    const long long ATTN_ELEMS = (long long)BATCH * NH * SEQ * SEQ;
    float* attn = ((long long)out_size >= OUT_ELEMS + ATTN_ELEMS) ? (outp + OUT_ELEMS)
                                                                  : attn_fb;

    static int inited = 0;
    if (!inited) {
        cudaFuncSetAttribute(gemm_h16, cudaFuncAttributeMaxDynamicSharedMemorySize, GSMEM_BYTES);
        inited = 1;
    }
    dim3 thr(256);

    // fp32 -> fp16 conversions (inputs + weights)
    conv(hidden,    hid16, (long long)ROWS * HID);
    conv(w_q_down,  wqd,   (long long)1536 * HID);
    conv(w_q_up,    wqup,  (long long)3072 * 1536);
    conv(w_kv_down, wkvd,  (long long)576 * HID);
    conv(w_kv_up,   wkvup, (long long)4096 * 512);
    conv(w_out,     wout,  (long long)HID * HID);

    // q = hidden @ w_q_down^T   [4096,1536] K=2048
    gemm_h16<<<dim3(1536/128, ROWS/128, 1), thr, GSMEM_BYTES>>>(
        hid16, wqd, qtmp, ROWS, 1536, HID, HID, HID, 1536,
        1, 0, 0, 0, 0, 0, 0, 1.0f, 0, 1);
    rmsnorm16<<<ROWS, 256>>>(qtmp, q_norm_w, 1536, 1536);

    // q = qn @ w_q_up^T   [4096,3072] K=1536
    gemm_h16<<<dim3(3072/128, ROWS/128, 1), thr, GSMEM_BYTES>>>(
        qtmp, wqup, qbig, ROWS, 3072, 1536, 1536, 1536, 3072,
        1, 0, 0, 0, 0, 0, 0, 1.0f, 0, 1);

    // c = hidden @ w_kv_down^T   [4096,576] K=2048
    gemm_h16<<<dim3((576 + 127)/128, ROWS/128, 1), thr, GSMEM_BYTES>>>(
        hid16, wkvd, c, ROWS, 576, HID, HID, HID, 576,
        1, 0, 0, 0, 0, 0, 0, 1.0f, 0, 1);
    rmsnorm16<<<ROWS, 256>>>(c, kv_norm_w, 512, 576);

    // kv = ckv_n @ w_kv_up^T   [4096,4096] K=512 (lda=576)
    gemm_h16<<<dim3(4096/128, ROWS/128, 1), thr, GSMEM_BYTES>>>(
        c, wkvup, kv, ROWS, 4096, 512, 576, 512, 4096,
        1, 0, 0, 0, 0, 0, 0, 1.0f, 0, 1);

    // RoPE + pack (V transposed)
    rope_pack16<<<ROWS, 256>>>(qbig, c, kv, Q, Kk, Vt);

    // scores = Q K^T / sqrt(192), causal tile-skip, batched over 32 (b,h), fp32 out
    float alpha = rsqrtf((float)DQK);
    gemm_h16<<<dim3(SEQ/128, SEQ/128, BATCH*NH), thr, GSMEM_BYTES>>>(
        Q, Kk, attn, SEQ, SEQ, DQK, DQK, DQK, SEQ,
        1, (long long)SEQ*DQK, 0,
        (long long)SEQ*DQK, 0,
        (long long)SEQ*SEQ, 0,
        alpha, 1, 0);

    // softmax -> fp32 attn (output) + trimmed fp16 copy
    softmax_causal<<<BATCH*NH*SEQ, 256>>>(attn, attn16);

    // ctx = attn16 @ Vt^T : NT, causal K-truncation, heavy-first, fp16 out
    gemm_h16<<<dim3(1, SEQ/128, BATCH*NH), thr, GSMEM_BYTES>>>(
        attn16, Vt, ctx, SEQ, DV, SEQ, SEQ, SEQ, NH*DV,
        NH,
        (long long)NH*SEQ*SEQ, (long long)SEQ*SEQ,
        (long long)NH*DV*SEQ,  (long long)DV*SEQ,
        (long long)SEQ*NH*DV,  (long long)DV,
        1.0f, 2, 1);

    // out = ctx @ w_out^T   [4096,2048] K=2048, fp32 out
    gemm_h16<<<dim3(HID/128, ROWS/128, 1), thr, GSMEM_BYTES>>>(
        ctx, wout, outp, ROWS, HID, NH*DV, NH*DV, NH*DV, HID,
        1, 0, 0, 0, 0, 0, 0, 1.0f, 0, 0);
}

// round 10
// speedup vs baseline: 6.7209x; 1.0690x over previous
#include <cuda_runtime.h>
#include <cuda_fp16.h>
#include <math.h>
#include <stdint.h>

#define BATCH 2
#define SEQ   2048
#define HID   2048
#define NH    16
#define DNOPE 128
#define DROPE 64
#define DV    128
#define DQK   192
#define LORA  512
#define ROWS  (BATCH*SEQ)   // 4096
#define NS    5             // cp.async pipeline stages (single-sync design)

// ---------------- scratch (static device memory; no allocations) ----------------
__device__ __half g_hidden16[(size_t)ROWS*HID];
__device__ __half g_wqd16 [(size_t)1536*HID];
__device__ __half g_wqup16[(size_t)3072*1536];
__device__ __half g_wkvd16[(size_t)576*HID];
__device__ __half g_wkvup16[(size_t)4096*512];
__device__ __half g_wout16[(size_t)HID*HID];
__device__ __half g_qtmp16[(size_t)ROWS*1536];
__device__ __half g_qbig16[(size_t)ROWS*3072];
__device__ __half g_c16   [(size_t)ROWS*576];
__device__ __half g_kv16  [(size_t)ROWS*4096];
__device__ __half g_Q16   [(size_t)BATCH*NH*SEQ*DQK];
__device__ __half g_K16   [(size_t)BATCH*NH*SEQ*DQK];
__device__ __half g_Vt16  [(size_t)BATCH*NH*DV*SEQ];   // V transposed per (b,h)
__device__ __half g_ctx16 [(size_t)ROWS*NH*DV];
__device__ __half g_attn16[(size_t)BATCH*NH*SEQ*SEQ];  // fp16 attn for attn@V
__device__ float  g_attn_fb[(size_t)BATCH*NH*SEQ*SEQ]; // fallback fp32 attn

__device__ __forceinline__ uint32_t smem_u32(const void* p) {
    uint32_t a;
    asm("{ .reg .u64 t; cvta.to.shared.u64 t, %1; cvt.u32.u64 %0, t; }" : "=r"(a) : "l"(p));
    return a;
}

#define MMA_F16(ac, ar, br)                                                       \
    asm volatile("mma.sync.aligned.m16n8k16.row.col.f32.f16.f16.f32 "             \
                 "{%0,%1,%2,%3}, {%4,%5,%6,%7}, {%8,%9}, {%0,%1,%2,%3};"          \
                 : "+f"((ac)[0]), "+f"((ac)[1]), "+f"((ac)[2]), "+f"((ac)[3])     \
                 : "r"((ar)[0]), "r"((ar)[1]), "r"((ar)[2]), "r"((ar)[3]),        \
                   "r"((br)[0]), "r"((br)[1]))

#define LDSM_X4(r0, r1, r2, r3, addr)                                             \
    asm volatile("ldmatrix.sync.aligned.m8n8.x4.shared.b16 {%0,%1,%2,%3}, [%4];"  \
                 : "=r"(r0), "=r"(r1), "=r"(r2), "=r"(r3) : "r"(addr))

// ---------------- fp32 -> fp16 conversion ----------------
__global__ __launch_bounds__(256) void f2h_kernel(
    const float4* __restrict__ src, uint2* __restrict__ dst, int n4)
{
    int i = blockIdx.x * blockDim.x + threadIdx.x;
    if (i < n4) {
        float4 v = src[i];
        __half2 a = __floats2half2_rn(v.x, v.y);
        __half2 b = __floats2half2_rn(v.z, v.w);
        dst[i] = make_uint2(*(uint32_t*)&a, *(uint32_t*)&b);
    }
}

// ---------------- fp16 mma.sync NT GEMM: cp.async.cg(16B) + ldmatrix.x4 ---------
// C[m,n] = alpha * sum_k A[m,k]*B[n,k] ; fp16 gmem, fp32 accumulate.
// CTA 128x128, BK=32, 8 warps (warp 64x32), 2 CTAs/SM, 5-stage single-sync pipe.
// SMEM: row = 32 halves (64B) = 4 x 16B units, unit swizzle u^((row>>1)&3) ->
// conflict-free ldmatrix phases + contiguous 16B cp.async granules (R8-verified).
// mode: 0 dense, 1 causal tile-skip, 2 causal K-truncation (heavy-first order).
// Merged-output support: tiles with n0 >= Nsplit switch to B2/C2/N2/ldc2
// (fuses q_down and kv_down, which share A, into one well-filled launch).
#define GSMEM_BYTES (NS * 16384)

__global__ __launch_bounds__(256, 2) void gemm_h16(
    const __half* __restrict__ A, const __half* __restrict__ B, void* __restrict__ Cv,
    int M, int N, int K, int lda, int ldb, int ldc,
    int zdiv, long long sA1, long long sA2,
    long long sB1, long long sB2, long long sC1, long long sC2,
    float alpha, int mode, int outhalf,
    const __half* __restrict__ B2, void* __restrict__ C2,
    int Nsplit, int N2, int ldc2)
{
    int z  = blockIdx.z;
    int my = (mode == 2) ? (gridDim.y - 1 - blockIdx.y) : blockIdx.y;  // heavy-first
    int m0 = my * 128;
    int n0 = blockIdx.x * 128;
    if (mode == 1 && n0 > m0) return;

    const __half* Ab = A + (long long)(z / zdiv) * sA1 + (long long)(z % zdiv) * sA2;
    const __half* Bb = B + (long long)(z / zdiv) * sB1 + (long long)(z % zdiv) * sB2;
    long long coff = (long long)(z / zdiv) * sC1 + (long long)(z % zdiv) * sC2;

    if (Nsplit > 0 && n0 >= Nsplit) {   // merged second output region
        Bb = B2; n0 -= Nsplit; N = N2; Cv = C2; ldc = ldc2; coff = 0;
    }

    extern __shared__ uint32_t sm[];
    uint32_t smb = smem_u32(sm);

    int t    = threadIdx.x;
    int lane = t & 31;
    int wid  = t >> 5;
    int g    = lane >> 2;
    int t4   = lane & 3;
    int wm   = wid >> 2;        // 0..1
    int wn   = wid & 3;         // 0..3

    int kEnd = K;
    if (mode == 2) { int ke = m0 + 128; kEnd = (ke < K) ? ke : K; }
    int nk = kEnd >> 5;

    float acc[4][4][4];
    #pragma unroll
    for (int mi = 0; mi < 4; mi++)
        #pragma unroll
        for (int ni = 0; ni < 4; ni++)
            #pragma unroll
            for (int r = 0; r < 4; r++) acc[mi][ni][r] = 0.0f;

    // ---- staging geometry: thread t covers 16B unit (row = t>>2 + 64*i, u = t&3)
    int urow = t >> 2;            // 0..63
    int uu   = t & 3;
    int sxu  = uu ^ ((urow >> 1) & 3);   // swizzled unit (invariant under row+=64)

    auto issue = [&](int kt, int st) {
        int k0 = kt << 5;
        uint32_t sA = smb + st * 16384;
        uint32_t sB = sA + 8192;
        #pragma unroll
        for (int i = 0; i < 2; i++) {
            int row = urow + i * 64;
            uint32_t dst = (uint32_t)(row * 64 + (sxu << 4));
            const __half* ga = Ab + (size_t)(m0 + row) * lda + k0 + uu * 8;
            asm volatile("cp.async.cg.shared.global [%0], [%1], 16;"
                         :: "r"(sA + dst), "l"(ga));
            int brow = n0 + row;
            const __half* gb = Bb + (size_t)(brow < N ? brow : 0) * ldb + k0 + uu * 8;
            int ssz = (brow < N) ? 16 : 0;
            asm volatile("cp.async.cg.shared.global [%0], [%1], 16, %2;"
                         :: "r"(sB + dst), "l"(gb), "r"(ssz));
        }
    };

    // ---- ldmatrix per-lane address components
    int m_idx = lane >> 3;        // matrix index 0..3
    int rin   = lane & 7;
    int arow0 = wm * 64 + rin + (m_idx & 1) * 8;
    int aun   = m_idx >> 1;                   // 0=klo,1=khi
    int axs   = (arow0 >> 1) & 3;
    uint32_t aoffb = (uint32_t)(arow0 * 64);
    int brow0 = wn * 32 + rin + (m_idx >> 1) * 8;
    int bun   = m_idx & 1;
    int bxs   = (brow0 >> 1) & 3;
    uint32_t boffb = (uint32_t)(brow0 * 64);

    auto mma_chunk = [&](int st) {
        uint32_t sA = smb + st * 16384;
        uint32_t sB = sA + 8192;
        #pragma unroll
        for (int ks = 0; ks < 2; ks++) {
            uint32_t af[4][4], bf[4][2];
            uint32_t au = (uint32_t)(((2 * ks + aun) ^ axs) << 4);
            uint32_t bu = (uint32_t)(((2 * ks + bun) ^ bxs) << 4);
            #pragma unroll
            for (int mi = 0; mi < 4; mi++)
                LDSM_X4(af[mi][0], af[mi][1], af[mi][2], af[mi][3],
                        sA + aoffb + (uint32_t)(mi * 1024) + au);
            #pragma unroll
            for (int p = 0; p < 2; p++)
                LDSM_X4(bf[2*p][0], bf[2*p][1], bf[2*p+1][0], bf[2*p+1][1],
                        sB + boffb + (uint32_t)(p * 1024) + bu);
            #pragma unroll
            for (int mi = 0; mi < 4; mi++)
                #pragma unroll
                for (int ni = 0; ni < 4; ni++)
                    MMA_F16(acc[mi][ni], af[mi], bf[ni]);
        }
    };

    // prologue
    #pragma unroll
    for (int s = 0; s < NS - 1; s++) {
        if (s < nk) issue(s, s);
        asm volatile("cp.async.commit_group;" ::: "memory");
    }

    int st = 0, stw = NS - 1;
    for (int kt = 0; kt < nk; kt++) {
        asm volatile("cp.async.wait_group %0;" :: "n"(NS - 2) : "memory");
        __syncthreads();
        mma_chunk(st);
        int nxt = kt + NS - 1;
        if (nxt < nk) issue(nxt, stw);
        asm volatile("cp.async.commit_group;" ::: "memory");
        if (++st == NS) st = 0;
        if (++stw == NS) stw = 0;
    }

    // epilogue
    #pragma unroll
    for (int mi = 0; mi < 4; mi++) {
        int row = m0 + wm * 64 + mi * 16 + g;
        #pragma unroll
        for (int ni = 0; ni < 4; ni++) {
            int col = n0 + wn * 32 + ni * 8 + 2 * t4;
            if (col < N) {
                if (outhalf) {
                    __half* Cb = (__half*)Cv + coff;
                    __half2 h0 = __floats2half2_rn(alpha * acc[mi][ni][0], alpha * acc[mi][ni][1]);
                    __half2 h1 = __floats2half2_rn(alpha * acc[mi][ni][2], alpha * acc[mi][ni][3]);
                    *(__half2*)(Cb + (size_t)row * ldc + col)       = h0;
                    *(__half2*)(Cb + (size_t)(row + 8) * ldc + col) = h1;
                } else {
                    float* Cb = (float*)Cv + coff;
                    float2 v0 = make_float2(alpha * acc[mi][ni][0], alpha * acc[mi][ni][1]);
                    float2 v1 = make_float2(alpha * acc[mi][ni][2], alpha * acc[mi][ni][3]);
                    *(float2*)(Cb + (size_t)row * ldc + col)       = v0;
                    *(float2*)(Cb + (size_t)(row + 8) * ldc + col) = v1;
                }
            }
        }
    }
}

// ---------------- block reductions (any blockDim multiple of 32) -----------------
__device__ __forceinline__ float blockReduceSum(float v) {
    __shared__ float sh[32];
    int lane = threadIdx.x & 31, w = threadIdx.x >> 5;
    #pragma unroll
    for (int o = 16; o > 0; o >>= 1) v += __shfl_xor_sync(0xffffffffu, v, o);
    __syncthreads();
    if (lane == 0) sh[w] = v;
    __syncthreads();
    int nw = (blockDim.x + 31) >> 5;
    float r = (threadIdx.x < nw) ? sh[threadIdx.x] : 0.0f;
    if (w == 0) {
        #pragma unroll
        for (int o = 16; o > 0; o >>= 1) r += __shfl_xor_sync(0xffffffffu, r, o);
        if (lane == 0) sh[0] = r;
    }
    __syncthreads();
    return sh[0];
}
__device__ __forceinline__ float blockReduceMax(float v) {
    __shared__ float sh[32];
    int lane = threadIdx.x & 31, w = threadIdx.x >> 5;
    #pragma unroll
    for (int o = 16; o > 0; o >>= 1) v = fmaxf(v, __shfl_xor_sync(0xffffffffu, v, o));
    __syncthreads();
    if (lane == 0) sh[w] = v;
    __syncthreads();
    int nw = (blockDim.x + 31) >> 5;
    float r = (threadIdx.x < nw) ? sh[threadIdx.x] : -INFINITY;
    if (w == 0) {
        #pragma unroll
        for (int o = 16; o > 0; o >>= 1) r = fmaxf(r, __shfl_xor_sync(0xffffffffu, r, o));
        if (lane == 0) sh[0] = r;
    }
    __syncthreads();
    return sh[0];
}

// ---------------- RMSNorm fp16 (in place) ----------------
__global__ __launch_bounds__(256) void rmsnorm16(
    __half* __restrict__ x, const float* __restrict__ w, int W, int stride)
{
    __half* row = x + (long long)blockIdx.x * stride;
    float ss = 0.0f;
    for (int i = threadIdx.x; i < W; i += blockDim.x) {
        float v = __half2float(row[i]); ss += v * v;
    }
    ss = blockReduceSum(ss);
    float sc = rsqrtf(ss / (float)W + 1e-6f);
    for (int i = threadIdx.x; i < W; i += blockDim.x)
        row[i] = __float2half(__half2float(row[i]) * sc * w[i]);
}

// ---------------- RoPE + pack fp16 (Q, K only; V handled by vtrans) -------------
__global__ __launch_bounds__(256) void rope_pack16(
    const __half* __restrict__ q,   // [ROWS,3072]
    const __half* __restrict__ c,   // [ROWS,576]
    const __half* __restrict__ kv,  // [ROWS,4096]
    __half* __restrict__ Qo,        // [B,NH,S,192]
    __half* __restrict__ Ko)        // [B,NH,S,192]
{
    int row = blockIdx.x;
    int b = row / SEQ, s = row % SEQ;
    int t = threadIdx.x;

    __shared__ float cs[32], sn[32];
    __shared__ __half kr[64];
    if (t < 32) {
        float f = exp10f(-(float)t / 8.0f);   // 10000^(-t/32)
        float ang = (float)s * f;
        sincosf(ang, &sn[t], &cs[t]);
    }
    __syncthreads();
    if (t < 64) {
        const __half* kx = c + (long long)row * 576 + 512;
        int j = t; float v;
        if (j < 32) v = __half2float(kx[2*j]) * cs[j] - __half2float(kx[2*j+1]) * sn[j];
        else { int i = j - 32; v = __half2float(kx[2*i+1]) * cs[i] + __half2float(kx[2*i]) * sn[i]; }
        kr[j] = __float2half(v);
    }
    __syncthreads();

    const __half* qrow = q + (long long)row * 3072;
    for (int idx = t; idx < NH * DQK; idx += 256) {
        int h = idx / DQK, d = idx % DQK;
        __half v;
        if (d < DNOPE) v = qrow[h * DQK + d];
        else {
            int j = d - DNOPE;
            const __half* qx = qrow + h * DQK + DNOPE;
            float vv;
            if (j < 32) vv = __half2float(qx[2*j]) * cs[j] - __half2float(qx[2*j+1]) * sn[j];
            else { int i = j - 32; vv = __half2float(qx[2*i+1]) * cs[i] + __half2float(qx[2*i]) * sn[i]; }
            v = __float2half(vv);
        }
        Qo[((long long)(b * NH + h) * SEQ + s) * DQK + d] = v;
    }

    const __half* kvrow = kv + (long long)row * 4096;
    for (int idx = t; idx < NH * DQK; idx += 256) {
        int h = idx / DQK, d = idx % DQK;
        __half v = (d < DNOPE) ? kvrow[h * 256 + d] : kr[d - DNOPE];
        Ko[((long long)(b * NH + h) * SEQ + s) * DQK + d] = v;
    }
}

// ---------------- V transpose: kv16[b,s,h,256](+128) -> Vt[bh, d, s] ------------
// Tiles 64(s) x 32(d), smem staged: coalesced loads along d, half2 stores along s.
__global__ __launch_bounds__(256) void vtrans(
    const __half* __restrict__ kv, __half* __restrict__ Vt)
{
    __shared__ __half tile[64][33];
    int s0 = blockIdx.x * 64;
    int d0 = blockIdx.y * 32;
    int z  = blockIdx.z;           // b*NH + h
    int b = z / NH, h = z % NH;
    int tx = threadIdx.x & 31;
    int ty = threadIdx.x >> 5;     // 0..7
    const __half* src = kv + (size_t)b * SEQ * 4096 + h * 256 + 128 + d0;
    #pragma unroll
    for (int k = 0; k < 8; k++) {
        int row = ty * 8 + k;
        tile[row][tx] = src[(size_t)(s0 + row) * 4096 + tx];
    }
    __syncthreads();
    #pragma unroll
    for (int k = 0; k < 4; k++) {
        int d = ty + 8 * k;
        __half2 v = __halves2half2(tile[2 * tx][d], tile[2 * tx + 1][d]);
        *(__half2*)&Vt[((size_t)z * DV + d0 + d) * SEQ + s0 + 2 * tx] = v;
    }
}

// ---------------- causal softmax: vectorized, fp32 out + trimmed fp16 copy -------
__global__ __launch_bounds__(256) void softmax_causal(
    float* __restrict__ attn, __half* __restrict__ attn16)
{
    long long r = blockIdx.x;
    int q = (int)(r % SEQ);
    float4* row4   = (float4*)(attn + r * SEQ);
    uint2*  row16  = (uint2*)(attn16 + r * SEQ);
    int t = threadIdx.x;
    int len = q + 1;
    int len16 = (len + 127) & ~127;   // attn@V never reads past the diagonal tile

    float4 v[2];
    float mx = -INFINITY;
    #pragma unroll
    for (int it = 0; it < 2; it++) {
        int i4 = t + it * 256;
        int base = i4 * 4;
        float4 x = make_float4(-INFINITY, -INFINITY, -INFINITY, -INFINITY);
        if (base < len) {
            x = row4[i4];
            if (base + 1 >= len) x.y = -INFINITY;
            if (base + 2 >= len) x.z = -INFINITY;
            if (base + 3 >= len) x.w = -INFINITY;
        }
        v[it] = x;
        mx = fmaxf(mx, fmaxf(fmaxf(x.x, x.y), fmaxf(x.z, x.w)));
    }
    mx = blockReduceMax(mx);

    float sum = 0.0f;
    #pragma unroll
    for (int it = 0; it < 2; it++) {
        float4 x = v[it];
        x.x = (x.x == -INFINITY) ? 0.0f : __expf(x.x - mx);
        x.y = (x.y == -INFINITY) ? 0.0f : __expf(x.y - mx);
        x.z = (x.z == -INFINITY) ? 0.0f : __expf(x.z - mx);
        x.w = (x.w == -INFINITY) ? 0.0f : __expf(x.w - mx);
        v[it] = x;
        sum += x.x + x.y + x.z + x.w;
    }
    sum = blockReduceSum(sum);
    float inv = 1.0f / sum;

    #pragma unroll
    for (int it = 0; it < 2; it++) {
        int i4 = t + it * 256;
        int base = i4 * 4;
        float4 x = v[it];
        x.x *= inv; x.y *= inv; x.z *= inv; x.w *= inv;
        row4[i4] = x;
        if (base < len16) {
            __half2 a = __floats2half2_rn(x.x, x.y);
            __half2 b = __floats2half2_rn(x.z, x.w);
            row16[i4] = make_uint2(*(uint32_t*)&a, *(uint32_t*)&b);
        }
    }
}

// ---------------- host launch ----------------
static inline void conv(const float* s, __half* d, long long n) {
    int n4 = (int)(n / 4);
    f2h_kernel<<<(n4 + 255) / 256, 256>>>((const float4*)s, (uint2*)d, n4);
}

extern "C" void kernel_launch(void* const* d_in, const int* in_sizes, int n_in,
                              void* d_out, int out_size) {
    const float* hidden    = (const float*)d_in[0];
    const float* w_q_down  = (const float*)d_in[3];
    const float* q_norm_w  = (const float*)d_in[4];
    const float* w_q_up    = (const float*)d_in[5];
    const float* w_kv_down = (const float*)d_in[6];
    const float* kv_norm_w = (const float*)d_in[7];
    const float* w_kv_up   = (const float*)d_in[8];
    const float* w_out     = (const float*)d_in[9];
    float* outp = (float*)d_out;

    void* p;
    __half *hid16, *wqd, *wqup, *wkvd, *wkvup, *wout;
    __half *qtmp, *qbig, *c, *kv, *Q, *Kk, *Vt, *ctx, *attn16;
    float* attn_fb;
    cudaGetSymbolAddress(&p, g_hidden16); hid16 = (__half*)p;
    cudaGetSymbolAddress(&p, g_wqd16);    wqd   = (__half*)p;
    cudaGetSymbolAddress(&p, g_wqup16);   wqup  = (__half*)p;
    cudaGetSymbolAddress(&p, g_wkvd16);   wkvd  = (__half*)p;
    cudaGetSymbolAddress(&p, g_wkvup16);  wkvup = (__half*)p;
    cudaGetSymbolAddress(&p, g_wout16);   wout  = (__half*)p;
    cudaGetSymbolAddress(&p, g_qtmp16);   qtmp  = (__half*)p;
    cudaGetSymbolAddress(&p, g_qbig16);   qbig  = (__half*)p;
    cudaGetSymbolAddress(&p, g_c16);      c     = (__half*)p;
    cudaGetSymbolAddress(&p, g_kv16);     kv    = (__half*)p;
    cudaGetSymbolAddress(&p, g_Q16);      Q     = (__half*)p;
    cudaGetSymbolAddress(&p, g_K16);      Kk    = (__half*)p;
    cudaGetSymbolAddress(&p, g_Vt16);     Vt    = (__half*)p;
    cudaGetSymbolAddress(&p, g_ctx16);    ctx   = (__half*)p;
    cudaGetSymbolAddress(&p, g_attn16);   attn16= (__half*)p;
    cudaGetSymbolAddress(&p, g_attn_fb);  attn_fb = (float*)p;

    const long long OUT_ELEMS  = (long long)ROWS * HID;
    const long long ATTN_ELEMS = (long long)BATCH * NH * SEQ * SEQ;
    float* attn = ((long long)out_size >= OUT_ELEMS + ATTN_ELEMS) ? (outp + OUT_ELEMS)
                                                                  : attn_fb;

    static int inited = 0;
    if (!inited) {
        cudaFuncSetAttribute(gemm_h16, cudaFuncAttributeMaxDynamicSharedMemorySize, GSMEM_BYTES);
        inited = 1;
    }
    dim3 thr(256);

    // conversions (ordered so launch index 5 is the merged down-proj GEMM for ncu)
    conv(hidden,    hid16, (long long)ROWS * HID);     // 0
    conv(w_q_down,  wqd,   (long long)1536 * HID);     // 1
    conv(w_kv_down, wkvd,  (long long)576 * HID);      // 2
    conv(w_q_up,    wqup,  (long long)3072 * 1536);    // 3
    conv(w_kv_up,   wkvup, (long long)4096 * 512);     // 4

    // merged down-proj: [q | kv] = hidden @ [w_q_down | w_kv_down]^T
    // tiles 0-11 -> qtmp (N=1536), tiles 12-16 -> c (N=576, ldc=576)
    gemm_h16<<<dim3(17, ROWS/128, 1), thr, GSMEM_BYTES>>>(   // 5  <- ncu target
        hid16, wqd, qtmp, ROWS, 1536, HID, HID, HID, 1536,
        1, 0, 0, 0, 0, 0, 0, 1.0f, 0, 1,
        wkvd, c, 1536, 576, 576);

    rmsnorm16<<<ROWS, 256>>>(qtmp, q_norm_w, 1536, 1536);
    rmsnorm16<<<ROWS, 256>>>(c, kv_norm_w, 512, 576);

    // q = qn @ w_q_up^T   [4096,3072] K=1536
    gemm_h16<<<dim3(3072/128, ROWS/128, 1), thr, GSMEM_BYTES>>>(
        qtmp, wqup, qbig, ROWS, 3072, 1536, 1536, 1536, 3072,
        1, 0, 0, 0, 0, 0, 0, 1.0f, 0, 1,
        (const __half*)0, (void*)0, 0, 0, 0);

    // kv = ckv_n @ w_kv_up^T   [4096,4096] K=512 (lda=576)
    gemm_h16<<<dim3(4096/128, ROWS/128, 1), thr, GSMEM_BYTES>>>(
        c, wkvup, kv, ROWS, 4096, 512, 576, 512, 4096,
        1, 0, 0, 0, 0, 0, 0, 1.0f, 0, 1,
        (const __half*)0, (void*)0, 0, 0, 0);

    conv(w_out, wout, (long long)HID * HID);

    // RoPE + pack Q/K ; V transposed separately (coalesced)
    rope_pack16<<<ROWS, 256>>>(qbig, c, kv, Q, Kk);
    vtrans<<<dim3(SEQ/64, DV/32, BATCH*NH), thr>>>(kv, Vt);

    // scores = Q K^T / sqrt(192), causal tile-skip, batched over 32 (b,h), fp32 out
    float alpha = rsqrtf((float)DQK);
    gemm_h16<<<dim3(SEQ/128, SEQ/128, BATCH*NH), thr, GSMEM_BYTES>>>(
        Q, Kk, attn, SEQ, SEQ, DQK, DQK, DQK, SEQ,
        1, (long long)SEQ*DQK, 0,
        (long long)SEQ*DQK, 0,
        (long long)SEQ*SEQ, 0,
        alpha, 1, 0,
        (const __half*)0, (void*)0, 0, 0, 0);

    // softmax -> fp32 attn (output) + trimmed fp16 copy
    softmax_causal<<<BATCH*NH*SEQ, 256>>>(attn, attn16);

    // ctx = attn16 @ Vt^T : NT, causal K-truncation, heavy-first, fp16 out
    gemm_h16<<<dim3(1, SEQ/128, BATCH*NH), thr, GSMEM_BYTES>>>(
        attn16, Vt, ctx, SEQ, DV, SEQ, SEQ, SEQ, NH*DV,
        NH,
        (long long)NH*SEQ*SEQ, (long long)SEQ*SEQ,
        (long long)NH*DV*SEQ,  (long long)DV*SEQ,
        (long long)SEQ*NH*DV,  (long long)DV,
        1.0f, 2, 1,
        (const __half*)0, (void*)0, 0, 0, 0);

    // out = ctx @ w_out^T   [4096,2048] K=2048, fp32 out
    gemm_h16<<<dim3(HID/128, ROWS/128, 1), thr, GSMEM_BYTES>>>(
        ctx, wout, outp, ROWS, HID, NH*DV, NH*DV, NH*DV, HID,
        1, 0, 0, 0, 0, 0, 0, 1.0f, 0, 0,
        (const __half*)0, (void*)0, 0, 0, 0);
}